// round 1
// baseline (speedup 1.0000x reference)
#include <cuda_runtime.h>
#include <cstdint>

#define ROI_SCALE 0.125f

// ---------------- scratch (device globals; no allocation allowed) ----------------
__device__ float g_zt [8ul*64*64*1280]; // NHWC transpose of z  (167.8 MB)
__device__ float g_X  [1024ul*1280];    // roi-align output
__device__ float g_H  [1024ul*5120];    // relu(X@W1+b1)
__device__ float g_CAT[1024ul*2048];    // [X2 | E] concat buffer

// ---------------- 1) transpose z: (8,1280,64,64) -> (8,4096,1280) ----------------
__global__ void transpose_kernel(const float* __restrict__ z)
{
    __shared__ float tile[32][33];
    const int b  = blockIdx.z;
    const int p0 = blockIdx.x * 32;   // pixel tile (h*64+w)
    const int c0 = blockIdx.y * 32;   // channel tile
    const float* src = z    + (size_t)b * 1280 * 4096;
    float*       dst = g_zt + (size_t)b * 4096 * 1280;
    const int tx = threadIdx.x, ty = threadIdx.y;
    #pragma unroll
    for (int i = 0; i < 4; i++)
        tile[ty + i*8][tx] = src[(size_t)(c0 + ty + i*8) * 4096 + p0 + tx];
    __syncthreads();
    #pragma unroll
    for (int i = 0; i < 4; i++)
        dst[(size_t)(p0 + ty + i*8) * 1280 + c0 + tx] = tile[tx][ty + i*8];
}

// ---------------- 2) RoIAlign 1x1 (one block per ROI, 256 threads) ----------------
__global__ void roi_align_kernel(const float* __restrict__ bboxes)
{
    __shared__ int   syl[8], syh[8], sxl[8], sxh[8];
    __shared__ float sfy[8], sfx[8], smy[8], smx[8];
    __shared__ int   sgh, sgw;
    __shared__ float sinv;

    const int r   = blockIdx.x;
    const int tid = threadIdx.x;

    if (tid == 0) {
        const float* bb = bboxes + (size_t)r * 4;
        float x1 = bb[0]*ROI_SCALE - 0.5f, y1 = bb[1]*ROI_SCALE - 0.5f;
        float x2 = bb[2]*ROI_SCALE - 0.5f, y2 = bb[3]*ROI_SCALE - 0.5f;
        float rw = x2 - x1, rh = y2 - y1;
        float gw = fminf(fmaxf(ceilf(rw), 1.f), 8.f);
        float gh = fminf(fmaxf(ceilf(rh), 1.f), 8.f);
        sgh = (int)gh; sgw = (int)gw;
        sinv = 1.f / (gh * gw);
        for (int i = 0; i < 8; i++) {
            // y axis (H = 64)
            float ys  = y1 + ((float)i + 0.5f) * rh / gh;
            bool  oy  = (ys < -1.f) || (ys > 64.f);
            float cy  = fmaxf(ys, 0.f);
            float ly0 = floorf(cy);
            bool  hcy = (ly0 >= 63.f);
            syl[i] = (int)fminf(ly0, 63.f);
            syh[i] = (int)fminf(ly0 + 1.f, 63.f);
            sfy[i] = hcy ? 0.f : (cy - ly0);
            smy[i] = (i < sgh && !oy) ? 1.f : 0.f;
            // x axis (W = 64)
            float xs  = x1 + ((float)i + 0.5f) * rw / gw;
            bool  ox  = (xs < -1.f) || (xs > 64.f);
            float cx  = fmaxf(xs, 0.f);
            float lx0 = floorf(cx);
            bool  hcx = (lx0 >= 63.f);
            sxl[i] = (int)fminf(lx0, 63.f);
            sxh[i] = (int)fminf(lx0 + 1.f, 63.f);
            sfx[i] = hcx ? 0.f : (cx - lx0);
            smx[i] = (i < sgw && !ox) ? 1.f : 0.f;
        }
    }
    __syncthreads();

    float acc[5] = {0.f, 0.f, 0.f, 0.f, 0.f};
    const int b = r >> 7;   // N = 128 rois per batch
    const float* base = g_zt + (size_t)b * 4096 * 1280 + tid;

    const int GH = sgh, GW = sgw;
    for (int gy = 0; gy < GH; gy++) {
        float my = smy[gy];
        if (my == 0.f) continue;
        const int yl = syl[gy], yh = syh[gy];
        const float fy = sfy[gy];
        for (int gx = 0; gx < GW; gx++) {
            float m = my * smx[gx];
            if (m == 0.f) continue;
            const int xl = sxl[gx], xh = sxh[gx];
            const float fx = sfx[gx];
            const float w00 = m * (1.f - fy) * (1.f - fx);
            const float w01 = m * (1.f - fy) * fx;
            const float w10 = m * fy * (1.f - fx);
            const float w11 = m * fy * fx;
            const float* p00 = base + (size_t)(yl*64 + xl) * 1280;
            const float* p01 = base + (size_t)(yl*64 + xh) * 1280;
            const float* p10 = base + (size_t)(yh*64 + xl) * 1280;
            const float* p11 = base + (size_t)(yh*64 + xh) * 1280;
            #pragma unroll
            for (int k = 0; k < 5; k++) {
                const int off = k * 256;
                acc[k] += w00 * p00[off];
                acc[k] += w01 * p01[off];
                acc[k] += w10 * p10[off];
                acc[k] += w11 * p11[off];
            }
        }
    }
    #pragma unroll
    for (int k = 0; k < 5; k++)
        g_X[(size_t)r * 1280 + tid + k * 256] = acc[k] * sinv;
}

// ---------------- 3) generic fp32 tiled GEMM: C = [relu](A@B + bias) ----------------
// A: MxK row-major (lda = K); B: KxN row-major; C row-major with stride ldc.
template<int BM, int BN, int BK, int TM, int TN, bool RELU>
__global__ __launch_bounds__((BM/TM)*(BN/TN))
void gemm_kernel(const float* __restrict__ A, const float* __restrict__ B,
                 const float* __restrict__ bias, float* __restrict__ C,
                 int M, int N, int K, int ldc)
{
    constexpr int THREADS = (BM/TM)*(BN/TN);
    constexpr int AF4 = BM*BK/4;
    constexpr int BF4 = BK*BN/4;
    static_assert(AF4 % THREADS == 0 && BF4 % THREADS == 0, "load mapping");

    __shared__ float As[BK][BM];
    __shared__ float Bs[BK][BN];

    const int tid  = threadIdx.x;
    const int brow = blockIdx.y, bcol = blockIdx.x;
    const float* Ab = A + (size_t)brow * BM * K;
    const float* Bb = B + (size_t)bcol * BN;
    float*       Cb = C + (size_t)brow * BM * ldc + (size_t)bcol * BN;
    const float* biasb = bias + (size_t)bcol * BN;

    const int tr = tid / (BN/TN);
    const int tc = tid % (BN/TN);

    float acc[TM][TN];
    #pragma unroll
    for (int i = 0; i < TM; i++)
        #pragma unroll
        for (int j = 0; j < TN; j++) acc[i][j] = 0.f;

    for (int t = 0; t < K; t += BK) {
        #pragma unroll
        for (int i = 0; i < AF4/THREADS; i++) {
            int f  = tid + i*THREADS;
            int m  = f / (BK/4);
            int kq = f % (BK/4);
            float4 v = *(const float4*)(Ab + (size_t)m * K + t + kq*4);
            As[kq*4+0][m] = v.x; As[kq*4+1][m] = v.y;
            As[kq*4+2][m] = v.z; As[kq*4+3][m] = v.w;
        }
        #pragma unroll
        for (int i = 0; i < BF4/THREADS; i++) {
            int f  = tid + i*THREADS;
            int k  = f / (BN/4);
            int nq = f % (BN/4);
            *(float4*)(&Bs[k][nq*4]) = *(const float4*)(Bb + (size_t)(t + k) * N + nq*4);
        }
        __syncthreads();
        #pragma unroll
        for (int k = 0; k < BK; k++) {
            float ra[TM], rb[TN];
            #pragma unroll
            for (int i = 0; i < TM; i++) ra[i] = As[k][tr*TM + i];
            #pragma unroll
            for (int j = 0; j < TN; j++) rb[j] = Bs[k][tc*TN + j];
            #pragma unroll
            for (int i = 0; i < TM; i++)
                #pragma unroll
                for (int j = 0; j < TN; j++)
                    acc[i][j] += ra[i] * rb[j];
        }
        __syncthreads();
    }

    #pragma unroll
    for (int i = 0; i < TM; i++) {
        #pragma unroll
        for (int j = 0; j < TN; j += 4) {
            float4 v;
            v.x = acc[i][j+0] + biasb[tc*TN + j + 0];
            v.y = acc[i][j+1] + biasb[tc*TN + j + 1];
            v.z = acc[i][j+2] + biasb[tc*TN + j + 2];
            v.w = acc[i][j+3] + biasb[tc*TN + j + 3];
            if (RELU) {
                v.x = fmaxf(v.x, 0.f); v.y = fmaxf(v.y, 0.f);
                v.z = fmaxf(v.z, 0.f); v.w = fmaxf(v.w, 0.f);
            }
            *(float4*)(Cb + (size_t)(tr*TM + i) * ldc + tc*TN + j) = v;
        }
    }
}

// ---------------- 4) bbox-size embedding MLP (16 ROIs per block) ----------------
// sz = [bh, bw]; e = relu(sz@S1+sb1); e = relu(e@S2+sb2); e = e@S3+sb3
// writes E into g_CAT[:, 1024:2048]
__global__ __launch_bounds__(256) void mlp_e_kernel(
    const float* __restrict__ bboxes,
    const float* __restrict__ S1, const float* __restrict__ sb1,
    const float* __restrict__ S2, const float* __restrict__ sb2,
    const float* __restrict__ S3, const float* __restrict__ sb3)
{
    __shared__ float e1[16][64];
    __shared__ float e2[16][256];
    __shared__ float sbh[16], sbw[16];

    const int r0  = blockIdx.x * 16;
    const int tid = threadIdx.x;

    if (tid < 16) {
        const float* bb = bboxes + (size_t)(r0 + tid) * 4;
        sbh[tid] = bb[3] - bb[1];   // height first (matches reference stack order)
        sbw[tid] = bb[2] - bb[0];
    }
    __syncthreads();

    // layer 1: (16 x 2) @ (2 x 64)
    for (int i = tid; i < 16*64; i += 256) {
        int row = i >> 6, col = i & 63;
        float v = sbh[row] * S1[col] + sbw[row] * S1[64 + col] + sb1[col];
        e1[row][col] = fmaxf(v, 0.f);
    }
    __syncthreads();

    // layer 2: (16 x 64) @ (64 x 256), one output column per thread
    {
        float a[16];
        const float bv = sb2[tid];
        #pragma unroll
        for (int r = 0; r < 16; r++) a[r] = bv;
        for (int k = 0; k < 64; k++) {
            const float s = S2[(size_t)k * 256 + tid];
            #pragma unroll
            for (int r = 0; r < 16; r++) a[r] += e1[r][k] * s;
        }
        #pragma unroll
        for (int r = 0; r < 16; r++) e2[r][tid] = fmaxf(a[r], 0.f);
    }
    __syncthreads();

    // layer 3: (16 x 256) @ (256 x 1024), 4 column chunks per thread
    for (int cc = 0; cc < 4; cc++) {
        const int col = tid + cc * 256;
        float a[16];
        const float bv = sb3[col];
        #pragma unroll
        for (int r = 0; r < 16; r++) a[r] = bv;
        for (int k = 0; k < 256; k++) {
            const float s = S3[(size_t)k * 1024 + col];
            #pragma unroll
            for (int r = 0; r < 16; r++) a[r] += e2[r][k] * s;
        }
        #pragma unroll
        for (int r = 0; r < 16; r++)
            g_CAT[(size_t)(r0 + r) * 2048 + 1024 + col] = a[r];
    }
}

// ---------------- launch ----------------
extern "C" void kernel_launch(void* const* d_in, const int* in_sizes, int n_in,
                              void* d_out, int out_size)
{
    const float* z      = (const float*)d_in[0];
    const float* bboxes = (const float*)d_in[1];
    const float* W1     = (const float*)d_in[2];
    const float* b1     = (const float*)d_in[3];
    const float* W2     = (const float*)d_in[4];
    const float* b2     = (const float*)d_in[5];
    const float* S1     = (const float*)d_in[6];
    const float* sb1    = (const float*)d_in[7];
    const float* S2     = (const float*)d_in[8];
    const float* sb2    = (const float*)d_in[9];
    const float* S3     = (const float*)d_in[10];
    const float* sb3    = (const float*)d_in[11];
    const float* O      = (const float*)d_in[12];
    const float* ob     = (const float*)d_in[13];
    float* out = (float*)d_out;

    float *X, *H, *CAT;
    cudaGetSymbolAddress((void**)&X,   g_X);
    cudaGetSymbolAddress((void**)&H,   g_H);
    cudaGetSymbolAddress((void**)&CAT, g_CAT);

    // 1) z NCHW -> NHWC
    transpose_kernel<<<dim3(128, 40, 8), dim3(32, 8)>>>(z);

    // 2) RoIAlign -> X (1024 x 1280)
    roi_align_kernel<<<1024, 256>>>(bboxes);

    // 5) bbox MLP -> CAT[:,1024:2048]   (independent; overlaps with GEMMs)
    mlp_e_kernel<<<64, 256>>>(bboxes, S1, sb1, S2, sb2, S3, sb3);

    // 3) H = relu(X @ W1 + b1)   (1024 x 5120, K=1280)
    gemm_kernel<128,128,8,8,8,true><<<dim3(5120/128, 1024/128), 256>>>(
        X, W1, b1, H, 1024, 5120, 1280, 5120);

    // 4) CAT[:,:1024] = H @ W2 + b2   (1024 x 1024, K=5120)
    gemm_kernel<128,64,16,8,4,false><<<dim3(1024/64, 1024/128), 256>>>(
        H, W2, b2, CAT, 1024, 1024, 5120, 2048);

    // 6) out = CAT @ O + ob   (1024 x 1024, K=2048)
    gemm_kernel<128,64,16,8,4,false><<<dim3(1024/64, 1024/128), 256>>>(
        CAT, O, ob, out, 1024, 1024, 2048, 1024);
}

// round 2
// speedup vs baseline: 1.6229x; 1.6229x over previous
#include <cuda_runtime.h>
#include <cuda_bf16.h>
#include <cstdint>

#define ROI_SCALE 0.125f

// ---------------- scratch (device globals; no allocation allowed) ----------------
__device__ float g_zt [8ul*64*64*1280];          // NHWC transpose of z
__device__ __nv_bfloat16 g_Xh [1024ul*1280];     // roi output hi
__device__ __nv_bfloat16 g_Xl [1024ul*1280];     // roi output lo
__device__ __nv_bfloat16 g_Hh [1024ul*5120];
__device__ __nv_bfloat16 g_Hl [1024ul*5120];
__device__ __nv_bfloat16 g_CATh[1024ul*2048];
__device__ __nv_bfloat16 g_CATl[1024ul*2048];
// transposed (N-major) bf16 hi/lo weights
__device__ __nv_bfloat16 g_W1th[5120ul*1280];
__device__ __nv_bfloat16 g_W1tl[5120ul*1280];
__device__ __nv_bfloat16 g_W2th[1024ul*5120];
__device__ __nv_bfloat16 g_W2tl[1024ul*5120];
__device__ __nv_bfloat16 g_Oth [1024ul*2048];
__device__ __nv_bfloat16 g_Otl [1024ul*2048];

// ---------------- helpers ----------------
__device__ __forceinline__ void bf16_split(float v, __nv_bfloat16& h, __nv_bfloat16& l) {
    h = __float2bfloat16(v);
    l = __float2bfloat16(v - __bfloat162float(h));
}

__device__ __forceinline__ void cpasync16(uint32_t saddr, const void* gaddr) {
    asm volatile("cp.async.ca.shared.global [%0], [%1], 16;\n" :: "r"(saddr), "l"(gaddr));
}

__device__ __forceinline__ void mma16816(float* c, const uint32_t* a, const uint32_t* b) {
    asm volatile(
        "mma.sync.aligned.m16n8k16.row.col.f32.bf16.bf16.f32 "
        "{%0,%1,%2,%3},{%4,%5,%6,%7},{%8,%9},{%0,%1,%2,%3};"
        : "+f"(c[0]), "+f"(c[1]), "+f"(c[2]), "+f"(c[3])
        : "r"(a[0]), "r"(a[1]), "r"(a[2]), "r"(a[3]), "r"(b[0]), "r"(b[1]));
}

// ---------------- 1) transpose z: (8,1280,64,64) -> (8,4096,1280) ----------------
__global__ void transpose_kernel(const float* __restrict__ z)
{
    __shared__ float tile[32][33];
    const int b  = blockIdx.z;
    const int p0 = blockIdx.x * 32;
    const int c0 = blockIdx.y * 32;
    const float* src = z    + (size_t)b * 1280 * 4096;
    float*       dst = g_zt + (size_t)b * 4096 * 1280;
    const int tx = threadIdx.x, ty = threadIdx.y;
    #pragma unroll
    for (int i = 0; i < 4; i++)
        tile[ty + i*8][tx] = src[(size_t)(c0 + ty + i*8) * 4096 + p0 + tx];
    __syncthreads();
    #pragma unroll
    for (int i = 0; i < 4; i++)
        dst[(size_t)(p0 + ty + i*8) * 1280 + c0 + tx] = tile[tx][ty + i*8];
}

// ---------------- 1b) weight convert + transpose: W[K][N] f32 -> Wt[N][K] bf16 hi/lo ----
__global__ void convt_kernel(const float* __restrict__ W,
                             __nv_bfloat16* __restrict__ Th,
                             __nv_bfloat16* __restrict__ Tl, int K, int N)
{
    __shared__ float tile[32][33];
    const int n0 = blockIdx.x * 32;
    const int k0 = blockIdx.y * 32;
    const int tx = threadIdx.x, ty = threadIdx.y;
    #pragma unroll
    for (int i = 0; i < 4; i++)
        tile[ty + i*8][tx] = W[(size_t)(k0 + ty + i*8) * N + n0 + tx];
    __syncthreads();
    #pragma unroll
    for (int i = 0; i < 4; i++) {
        float v = tile[tx][ty + i*8];
        __nv_bfloat16 h, l; bf16_split(v, h, l);
        size_t idx = (size_t)(n0 + ty + i*8) * K + k0 + tx;
        Th[idx] = h; Tl[idx] = l;
    }
}

// ---------------- 2) RoIAlign 1x1 (one block per ROI, 256 threads) ----------------
__global__ void roi_align_kernel(const float* __restrict__ bboxes)
{
    __shared__ int   syl[8], syh[8], sxl[8], sxh[8];
    __shared__ float sfy[8], sfx[8], smy[8], smx[8];
    __shared__ int   sgh, sgw;
    __shared__ float sinv;

    const int r   = blockIdx.x;
    const int tid = threadIdx.x;

    if (tid == 0) {
        const float* bb = bboxes + (size_t)r * 4;
        float x1 = bb[0]*ROI_SCALE - 0.5f, y1 = bb[1]*ROI_SCALE - 0.5f;
        float x2 = bb[2]*ROI_SCALE - 0.5f, y2 = bb[3]*ROI_SCALE - 0.5f;
        float rw = x2 - x1, rh = y2 - y1;
        float gw = fminf(fmaxf(ceilf(rw), 1.f), 8.f);
        float gh = fminf(fmaxf(ceilf(rh), 1.f), 8.f);
        sgh = (int)gh; sgw = (int)gw;
        sinv = 1.f / (gh * gw);
        for (int i = 0; i < 8; i++) {
            float ys  = y1 + ((float)i + 0.5f) * rh / gh;
            bool  oy  = (ys < -1.f) || (ys > 64.f);
            float cy  = fmaxf(ys, 0.f);
            float ly0 = floorf(cy);
            bool  hcy = (ly0 >= 63.f);
            syl[i] = (int)fminf(ly0, 63.f);
            syh[i] = (int)fminf(ly0 + 1.f, 63.f);
            sfy[i] = hcy ? 0.f : (cy - ly0);
            smy[i] = (i < sgh && !oy) ? 1.f : 0.f;
            float xs  = x1 + ((float)i + 0.5f) * rw / gw;
            bool  ox  = (xs < -1.f) || (xs > 64.f);
            float cx  = fmaxf(xs, 0.f);
            float lx0 = floorf(cx);
            bool  hcx = (lx0 >= 63.f);
            sxl[i] = (int)fminf(lx0, 63.f);
            sxh[i] = (int)fminf(lx0 + 1.f, 63.f);
            sfx[i] = hcx ? 0.f : (cx - lx0);
            smx[i] = (i < sgw && !ox) ? 1.f : 0.f;
        }
    }
    __syncthreads();

    float acc[5] = {0.f, 0.f, 0.f, 0.f, 0.f};
    const int b = r >> 7;
    const float* base = g_zt + (size_t)b * 4096 * 1280 + tid;

    const int GH = sgh, GW = sgw;
    for (int gy = 0; gy < GH; gy++) {
        float my = smy[gy];
        if (my == 0.f) continue;
        const int yl = syl[gy], yh = syh[gy];
        const float fy = sfy[gy];
        for (int gx = 0; gx < GW; gx++) {
            float m = my * smx[gx];
            if (m == 0.f) continue;
            const int xl = sxl[gx], xh = sxh[gx];
            const float fx = sfx[gx];
            const float w00 = m * (1.f - fy) * (1.f - fx);
            const float w01 = m * (1.f - fy) * fx;
            const float w10 = m * fy * (1.f - fx);
            const float w11 = m * fy * fx;
            const float* p00 = base + (size_t)(yl*64 + xl) * 1280;
            const float* p01 = base + (size_t)(yl*64 + xh) * 1280;
            const float* p10 = base + (size_t)(yh*64 + xl) * 1280;
            const float* p11 = base + (size_t)(yh*64 + xh) * 1280;
            #pragma unroll
            for (int k = 0; k < 5; k++) {
                const int off = k * 256;
                acc[k] += w00 * p00[off];
                acc[k] += w01 * p01[off];
                acc[k] += w10 * p10[off];
                acc[k] += w11 * p11[off];
            }
        }
    }
    #pragma unroll
    for (int k = 0; k < 5; k++) {
        float v = acc[k] * sinv;
        __nv_bfloat16 h, l; bf16_split(v, h, l);
        size_t idx = (size_t)r * 1280 + tid + k * 256;
        g_Xh[idx] = h; g_Xl[idx] = l;
    }
}

// ---------------- 3) bf16-split tensor-core GEMM ----------------
// C(MxN) = [relu](A(MxK) @ B(KxN) + bias), A given as hi/lo bf16 row-major,
// B given as hi/lo bf16 N-major (Bt[n][k]).
// OUT: 0 = fp32 store (no relu), 1 = relu + bf16 hi/lo store, 2 = bf16 hi/lo store
#define BM 128
#define BK 16
#define ASTRIDE 24   // bf16 elems per smem row (16 + 8 pad -> conflict-free frag LDS)

template<int BN, int OUT>
__global__ __launch_bounds__(2*BN)
void mma_gemm(const __nv_bfloat16* __restrict__ Ah, const __nv_bfloat16* __restrict__ Al,
              const __nv_bfloat16* __restrict__ Bh, const __nv_bfloat16* __restrict__ Bl,
              const float* __restrict__ bias,
              float* __restrict__ Cf,
              __nv_bfloat16* __restrict__ Ch, __nv_bfloat16* __restrict__ Cl,
              int K, int ldc)
{
    constexpr int THREADS = 2 * BN;
    constexpr int WARPS_N = BN / 32;
    constexpr int ACH = BM * 2;      // 16B chunks per A tile (per hi/lo)
    constexpr int BCH = BN * 2;

    __shared__ __nv_bfloat16 As[2][2][BM * ASTRIDE];
    __shared__ __nv_bfloat16 Bs[2][2][BN * ASTRIDE];

    const int tid  = threadIdx.x;
    const int wid  = tid >> 5, lane = tid & 31;
    const int wm   = (wid / WARPS_N) * 64;
    const int wn   = (wid % WARPS_N) * 32;
    const int qrow = lane >> 2, qcol = lane & 3;
    const int m0   = blockIdx.y * BM;
    const int n0   = blockIdx.x * BN;

    float acc[4][4][4];
    #pragma unroll
    for (int i = 0; i < 4; i++)
        #pragma unroll
        for (int j = 0; j < 4; j++)
            #pragma unroll
            for (int q = 0; q < 4; q++) acc[i][j][q] = 0.f;

    const uint32_t sA = (uint32_t)__cvta_generic_to_shared(&As[0][0][0]);
    const uint32_t sB = (uint32_t)__cvta_generic_to_shared(&Bs[0][0][0]);

    auto load_stage = [&](int st, int kk) {
        #pragma unroll
        for (int i = 0; i < ACH / THREADS; i++) {
            int f = tid + i * THREADS;
            int row = f >> 1, half = f & 1;
            uint32_t soff = (uint32_t)((row * ASTRIDE + half * 8) * 2);
            size_t goff = (size_t)(m0 + row) * K + kk + half * 8;
            cpasync16(sA + (st*2 + 0) * (BM*ASTRIDE*2) + soff, Ah + goff);
            cpasync16(sA + (st*2 + 1) * (BM*ASTRIDE*2) + soff, Al + goff);
        }
        #pragma unroll
        for (int i = 0; i < BCH / THREADS; i++) {
            int f = tid + i * THREADS;
            int row = f >> 1, half = f & 1;
            uint32_t soff = (uint32_t)((row * ASTRIDE + half * 8) * 2);
            size_t goff = (size_t)(n0 + row) * K + kk + half * 8;
            cpasync16(sB + (st*2 + 0) * (BN*ASTRIDE*2) + soff, Bh + goff);
            cpasync16(sB + (st*2 + 1) * (BN*ASTRIDE*2) + soff, Bl + goff);
        }
        asm volatile("cp.async.commit_group;\n" ::: "memory");
    };

    load_stage(0, 0);
    const int nsteps = K / BK;

    for (int s = 0; s < nsteps; s++) {
        asm volatile("cp.async.wait_group 0;\n" ::: "memory");
        __syncthreads();
        if (s + 1 < nsteps) load_stage((s + 1) & 1, (s + 1) * BK);

        const int st = s & 1;
        const __nv_bfloat16* Ash = As[st][0];
        const __nv_bfloat16* Asl = As[st][1];
        const __nv_bfloat16* Bsh = Bs[st][0];
        const __nv_bfloat16* Bsl = Bs[st][1];

        uint32_t bh[4][2], bl[4][2];
        #pragma unroll
        for (int nt = 0; nt < 4; nt++) {
            int n = wn + nt * 8 + qrow;
            bh[nt][0] = *(const uint32_t*)(Bsh + n * ASTRIDE + qcol * 2);
            bh[nt][1] = *(const uint32_t*)(Bsh + n * ASTRIDE + qcol * 2 + 8);
            bl[nt][0] = *(const uint32_t*)(Bsl + n * ASTRIDE + qcol * 2);
            bl[nt][1] = *(const uint32_t*)(Bsl + n * ASTRIDE + qcol * 2 + 8);
        }
        #pragma unroll
        for (int mt = 0; mt < 4; mt++) {
            int m = wm + mt * 16 + qrow;
            uint32_t ah[4], al[4];
            ah[0] = *(const uint32_t*)(Ash + m       * ASTRIDE + qcol * 2);
            ah[1] = *(const uint32_t*)(Ash + (m + 8) * ASTRIDE + qcol * 2);
            ah[2] = *(const uint32_t*)(Ash + m       * ASTRIDE + qcol * 2 + 8);
            ah[3] = *(const uint32_t*)(Ash + (m + 8) * ASTRIDE + qcol * 2 + 8);
            al[0] = *(const uint32_t*)(Asl + m       * ASTRIDE + qcol * 2);
            al[1] = *(const uint32_t*)(Asl + (m + 8) * ASTRIDE + qcol * 2);
            al[2] = *(const uint32_t*)(Asl + m       * ASTRIDE + qcol * 2 + 8);
            al[3] = *(const uint32_t*)(Asl + (m + 8) * ASTRIDE + qcol * 2 + 8);
            #pragma unroll
            for (int nt = 0; nt < 4; nt++) {
                mma16816(acc[mt][nt], ah, bh[nt]);
                mma16816(acc[mt][nt], al, bh[nt]);
                mma16816(acc[mt][nt], ah, bl[nt]);
            }
        }
        __syncthreads();
    }

    // epilogue
    #pragma unroll
    for (int mt = 0; mt < 4; mt++) {
        int r0 = m0 + wm + mt * 16 + qrow;
        #pragma unroll
        for (int nt = 0; nt < 4; nt++) {
            int c = n0 + wn + nt * 8 + qcol * 2;
            float bv0 = bias[c], bv1 = bias[c + 1];
            float v00 = acc[mt][nt][0] + bv0;
            float v01 = acc[mt][nt][1] + bv1;
            float v10 = acc[mt][nt][2] + bv0;
            float v11 = acc[mt][nt][3] + bv1;
            if (OUT == 1) {
                v00 = fmaxf(v00, 0.f); v01 = fmaxf(v01, 0.f);
                v10 = fmaxf(v10, 0.f); v11 = fmaxf(v11, 0.f);
            }
            if (OUT == 0) {
                size_t i0 = (size_t)r0 * ldc + c;
                size_t i1 = (size_t)(r0 + 8) * ldc + c;
                Cf[i0] = v00; Cf[i0 + 1] = v01;
                Cf[i1] = v10; Cf[i1 + 1] = v11;
            } else {
                __nv_bfloat16 h0, l0, h1, l1;
                size_t i0 = (size_t)r0 * ldc + c;
                bf16_split(v00, h0, l0); bf16_split(v01, h1, l1);
                *(__nv_bfloat162*)(Ch + i0) = __halves2bfloat162(h0, h1);
                *(__nv_bfloat162*)(Cl + i0) = __halves2bfloat162(l0, l1);
                size_t i1 = (size_t)(r0 + 8) * ldc + c;
                bf16_split(v10, h0, l0); bf16_split(v11, h1, l1);
                *(__nv_bfloat162*)(Ch + i1) = __halves2bfloat162(h0, h1);
                *(__nv_bfloat162*)(Cl + i1) = __halves2bfloat162(l0, l1);
            }
        }
    }
}

// ---------------- 4) bbox-size embedding MLP (16 ROIs per block) ----------------
__global__ __launch_bounds__(256) void mlp_e_kernel(
    const float* __restrict__ bboxes,
    const float* __restrict__ S1, const float* __restrict__ sb1,
    const float* __restrict__ S2, const float* __restrict__ sb2,
    const float* __restrict__ S3, const float* __restrict__ sb3)
{
    __shared__ float e1[16][64];
    __shared__ float e2[16][256];
    __shared__ float sbh[16], sbw[16];

    const int r0  = blockIdx.x * 16;
    const int tid = threadIdx.x;

    if (tid < 16) {
        const float* bb = bboxes + (size_t)(r0 + tid) * 4;
        sbh[tid] = bb[3] - bb[1];
        sbw[tid] = bb[2] - bb[0];
    }
    __syncthreads();

    for (int i = tid; i < 16*64; i += 256) {
        int row = i >> 6, col = i & 63;
        float v = sbh[row] * S1[col] + sbw[row] * S1[64 + col] + sb1[col];
        e1[row][col] = fmaxf(v, 0.f);
    }
    __syncthreads();

    {
        float a[16];
        const float bv = sb2[tid];
        #pragma unroll
        for (int r = 0; r < 16; r++) a[r] = bv;
        for (int k = 0; k < 64; k++) {
            const float s = S2[(size_t)k * 256 + tid];
            #pragma unroll
            for (int r = 0; r < 16; r++) a[r] += e1[r][k] * s;
        }
        #pragma unroll
        for (int r = 0; r < 16; r++) e2[r][tid] = fmaxf(a[r], 0.f);
    }
    __syncthreads();

    for (int cc = 0; cc < 4; cc++) {
        const int col = tid + cc * 256;
        float a[16];
        const float bv = sb3[col];
        #pragma unroll
        for (int r = 0; r < 16; r++) a[r] = bv;
        for (int k = 0; k < 256; k++) {
            const float s = S3[(size_t)k * 1024 + col];
            #pragma unroll
            for (int r = 0; r < 16; r++) a[r] += e2[r][k] * s;
        }
        #pragma unroll
        for (int r = 0; r < 16; r++) {
            float v = a[r];
            __nv_bfloat16 h, l; bf16_split(v, h, l);
            size_t idx = (size_t)(r0 + r) * 2048 + 1024 + col;
            g_CATh[idx] = h; g_CATl[idx] = l;
        }
    }
}

// ---------------- launch ----------------
extern "C" void kernel_launch(void* const* d_in, const int* in_sizes, int n_in,
                              void* d_out, int out_size)
{
    const float* z      = (const float*)d_in[0];
    const float* bboxes = (const float*)d_in[1];
    const float* W1     = (const float*)d_in[2];
    const float* b1     = (const float*)d_in[3];
    const float* W2     = (const float*)d_in[4];
    const float* b2     = (const float*)d_in[5];
    const float* S1     = (const float*)d_in[6];
    const float* sb1    = (const float*)d_in[7];
    const float* S2     = (const float*)d_in[8];
    const float* sb2    = (const float*)d_in[9];
    const float* S3     = (const float*)d_in[10];
    const float* sb3    = (const float*)d_in[11];
    const float* O      = (const float*)d_in[12];
    const float* ob     = (const float*)d_in[13];
    float* out = (float*)d_out;

    __nv_bfloat16 *Xh, *Xl, *Hh, *Hl, *CATh, *CATl;
    __nv_bfloat16 *W1th, *W1tl, *W2th, *W2tl, *Oth, *Otl;
    cudaGetSymbolAddress((void**)&Xh,   g_Xh);
    cudaGetSymbolAddress((void**)&Xl,   g_Xl);
    cudaGetSymbolAddress((void**)&Hh,   g_Hh);
    cudaGetSymbolAddress((void**)&Hl,   g_Hl);
    cudaGetSymbolAddress((void**)&CATh, g_CATh);
    cudaGetSymbolAddress((void**)&CATl, g_CATl);
    cudaGetSymbolAddress((void**)&W1th, g_W1th);
    cudaGetSymbolAddress((void**)&W1tl, g_W1tl);
    cudaGetSymbolAddress((void**)&W2th, g_W2th);
    cudaGetSymbolAddress((void**)&W2tl, g_W2tl);
    cudaGetSymbolAddress((void**)&Oth,  g_Oth);
    cudaGetSymbolAddress((void**)&Otl,  g_Otl);

    // weight conversion + transpose (independent of z/bboxes work)
    convt_kernel<<<dim3(5120/32, 1280/32), dim3(32, 8)>>>(W1, W1th, W1tl, 1280, 5120);
    convt_kernel<<<dim3(1024/32, 5120/32), dim3(32, 8)>>>(W2, W2th, W2tl, 5120, 1024);
    convt_kernel<<<dim3(1024/32, 2048/32), dim3(32, 8)>>>(O,  Oth,  Otl,  2048, 1024);

    // z NCHW -> NHWC
    transpose_kernel<<<dim3(128, 40, 8), dim3(32, 8)>>>(z);

    // RoIAlign -> X hi/lo (1024 x 1280)
    roi_align_kernel<<<1024, 256>>>(bboxes);

    // bbox MLP -> CAT[:,1024:2048] hi/lo
    mlp_e_kernel<<<64, 256>>>(bboxes, S1, sb1, S2, sb2, S3, sb3);

    // H = relu(X @ W1 + b1)   (1024 x 5120, K=1280)
    mma_gemm<128, 1><<<dim3(5120/128, 1024/128), 256>>>(
        Xh, Xl, W1th, W1tl, b1, nullptr, Hh, Hl, 1280, 5120);

    // CAT[:, :1024] = H @ W2 + b2   (1024 x 1024, K=5120)
    mma_gemm<64, 2><<<dim3(1024/64, 1024/128), 128>>>(
        Hh, Hl, W2th, W2tl, b2, nullptr, CATh, CATl, 5120, 2048);

    // out = CAT @ O + ob   (1024 x 1024, K=2048)
    mma_gemm<64, 0><<<dim3(1024/64, 1024/128), 128>>>(
        CATh, CATl, Oth, Otl, ob, out, nullptr, nullptr, 2048, 1024);
}

// round 4
// speedup vs baseline: 2.0131x; 1.2405x over previous
#include <cuda_runtime.h>
#include <cuda_bf16.h>
#include <cstdint>

#define ROI_SCALE 0.125f

// ---------------- scratch (device globals; no allocation allowed) ----------------
__device__ float g_zt [8ul*64*64*1280];          // NHWC transpose of z
__device__ __nv_bfloat16 g_Xh [1024ul*1280];
__device__ __nv_bfloat16 g_Xl [1024ul*1280];
__device__ __nv_bfloat16 g_Hh [1024ul*5120];
__device__ __nv_bfloat16 g_Hl [1024ul*5120];
__device__ __nv_bfloat16 g_CATh[1024ul*2048];
__device__ __nv_bfloat16 g_CATl[1024ul*2048];
__device__ __nv_bfloat16 g_W1th[5120ul*1280];
__device__ __nv_bfloat16 g_W1tl[5120ul*1280];
__device__ __nv_bfloat16 g_W2th[1024ul*5120];
__device__ __nv_bfloat16 g_W2tl[1024ul*5120];
__device__ __nv_bfloat16 g_Oth [1024ul*2048];
__device__ __nv_bfloat16 g_Otl [1024ul*2048];

// ---------------- helpers ----------------
__device__ __forceinline__ void bf16_split(float v, __nv_bfloat16& h, __nv_bfloat16& l) {
    h = __float2bfloat16(v);
    l = __float2bfloat16(v - __bfloat162float(h));
}

__device__ __forceinline__ void cpasync16(uint32_t saddr, const void* gaddr) {
    asm volatile("cp.async.cg.shared.global [%0], [%1], 16;\n" :: "r"(saddr), "l"(gaddr));
}

__device__ __forceinline__ void ldsm4(uint32_t* r, uint32_t a) {
    asm volatile("ldmatrix.sync.aligned.m8n8.x4.shared.b16 {%0,%1,%2,%3}, [%4];"
                 : "=r"(r[0]), "=r"(r[1]), "=r"(r[2]), "=r"(r[3]) : "r"(a));
}

__device__ __forceinline__ void mma16816(float* c, const uint32_t* a, const uint32_t* b) {
    asm volatile(
        "mma.sync.aligned.m16n8k16.row.col.f32.bf16.bf16.f32 "
        "{%0,%1,%2,%3},{%4,%5,%6,%7},{%8,%9},{%0,%1,%2,%3};"
        : "+f"(c[0]), "+f"(c[1]), "+f"(c[2]), "+f"(c[3])
        : "r"(a[0]), "r"(a[1]), "r"(a[2]), "r"(a[3]), "r"(b[0]), "r"(b[1]));
}

// ---------------- 1) transpose z: (8,1280,64,64) -> (8,4096,1280) ----------------
__global__ void transpose_kernel(const float* __restrict__ z)
{
    __shared__ float tile[32][33];
    const int b  = blockIdx.z;
    const int p0 = blockIdx.x * 32;
    const int c0 = blockIdx.y * 32;
    const float* src = z    + (size_t)b * 1280 * 4096;
    float*       dst = g_zt + (size_t)b * 4096 * 1280;
    const int tx = threadIdx.x, ty = threadIdx.y;
    #pragma unroll
    for (int i = 0; i < 4; i++)
        tile[ty + i*8][tx] = src[(size_t)(c0 + ty + i*8) * 4096 + p0 + tx];
    __syncthreads();
    #pragma unroll
    for (int i = 0; i < 4; i++)
        dst[(size_t)(p0 + ty + i*8) * 1280 + c0 + tx] = tile[tx][ty + i*8];
}

// ---------------- 1b) weight convert + transpose ----------------
__global__ void convt_kernel(const float* __restrict__ W,
                             __nv_bfloat16* __restrict__ Th,
                             __nv_bfloat16* __restrict__ Tl, int K, int N)
{
    __shared__ float tile[32][33];
    const int n0 = blockIdx.x * 32;
    const int k0 = blockIdx.y * 32;
    const int tx = threadIdx.x, ty = threadIdx.y;
    #pragma unroll
    for (int i = 0; i < 4; i++)
        tile[ty + i*8][tx] = W[(size_t)(k0 + ty + i*8) * N + n0 + tx];
    __syncthreads();
    #pragma unroll
    for (int i = 0; i < 4; i++) {
        float v = tile[tx][ty + i*8];
        __nv_bfloat16 h, l; bf16_split(v, h, l);
        size_t idx = (size_t)(n0 + ty + i*8) * K + k0 + tx;
        Th[idx] = h; Tl[idx] = l;
    }
}

// ---------------- 2) RoIAlign 1x1 ----------------
__global__ void roi_align_kernel(const float* __restrict__ bboxes)
{
    __shared__ int   syl[8], syh[8], sxl[8], sxh[8];
    __shared__ float sfy[8], sfx[8], smy[8], smx[8];
    __shared__ int   sgh, sgw;
    __shared__ float sinv;

    const int r   = blockIdx.x;
    const int tid = threadIdx.x;

    if (tid == 0) {
        const float* bb = bboxes + (size_t)r * 4;
        float x1 = bb[0]*ROI_SCALE - 0.5f, y1 = bb[1]*ROI_SCALE - 0.5f;
        float x2 = bb[2]*ROI_SCALE - 0.5f, y2 = bb[3]*ROI_SCALE - 0.5f;
        float rw = x2 - x1, rh = y2 - y1;
        float gw = fminf(fmaxf(ceilf(rw), 1.f), 8.f);
        float gh = fminf(fmaxf(ceilf(rh), 1.f), 8.f);
        sgh = (int)gh; sgw = (int)gw;
        sinv = 1.f / (gh * gw);
        for (int i = 0; i < 8; i++) {
            float ys  = y1 + ((float)i + 0.5f) * rh / gh;
            bool  oy  = (ys < -1.f) || (ys > 64.f);
            float cy  = fmaxf(ys, 0.f);
            float ly0 = floorf(cy);
            bool  hcy = (ly0 >= 63.f);
            syl[i] = (int)fminf(ly0, 63.f);
            syh[i] = (int)fminf(ly0 + 1.f, 63.f);
            sfy[i] = hcy ? 0.f : (cy - ly0);
            smy[i] = (i < sgh && !oy) ? 1.f : 0.f;
            float xs  = x1 + ((float)i + 0.5f) * rw / gw;
            bool  ox  = (xs < -1.f) || (xs > 64.f);
            float cx  = fmaxf(xs, 0.f);
            float lx0 = floorf(cx);
            bool  hcx = (lx0 >= 63.f);
            sxl[i] = (int)fminf(lx0, 63.f);
            sxh[i] = (int)fminf(lx0 + 1.f, 63.f);
            sfx[i] = hcx ? 0.f : (cx - lx0);
            smx[i] = (i < sgw && !ox) ? 1.f : 0.f;
        }
    }
    __syncthreads();

    float acc[5] = {0.f, 0.f, 0.f, 0.f, 0.f};
    const int b = r >> 7;
    const float* base = g_zt + (size_t)b * 4096 * 1280 + tid;

    const int GH = sgh, GW = sgw;
    for (int gy = 0; gy < GH; gy++) {
        float my = smy[gy];
        if (my == 0.f) continue;
        const int yl = syl[gy], yh = syh[gy];
        const float fy = sfy[gy];
        for (int gx = 0; gx < GW; gx++) {
            float m = my * smx[gx];
            if (m == 0.f) continue;
            const int xl = sxl[gx], xh = sxh[gx];
            const float fx = sfx[gx];
            const float w00 = m * (1.f - fy) * (1.f - fx);
            const float w01 = m * (1.f - fy) * fx;
            const float w10 = m * fy * (1.f - fx);
            const float w11 = m * fy * fx;
            const float* p00 = base + (size_t)(yl*64 + xl) * 1280;
            const float* p01 = base + (size_t)(yl*64 + xh) * 1280;
            const float* p10 = base + (size_t)(yh*64 + xl) * 1280;
            const float* p11 = base + (size_t)(yh*64 + xh) * 1280;
            #pragma unroll
            for (int k = 0; k < 5; k++) {
                const int off = k * 256;
                acc[k] += w00 * p00[off];
                acc[k] += w01 * p01[off];
                acc[k] += w10 * p10[off];
                acc[k] += w11 * p11[off];
            }
        }
    }
    #pragma unroll
    for (int k = 0; k < 5; k++) {
        float v = acc[k] * sinv;
        __nv_bfloat16 h, l; bf16_split(v, h, l);
        size_t idx = (size_t)r * 1280 + tid + k * 256;
        g_Xh[idx] = h; g_Xl[idx] = l;
    }
}

// ---------------- 3) bf16-split mma.sync GEMM, ldmatrix + BK=32 ----------------
// C(MxN) = [relu](A@B + bias). A row-major hi/lo bf16, B N-major hi/lo bf16.
// CTA tile BM x 128, 8 warps as 2(m) x 4(n); warp tile (BM/2) x 32.
// Smem rows padded to 80B (64B data) -> conflict-free LDSM & cp.async.
// OUT: 0 = fp32 store, 1 = relu + bf16 hi/lo, 2 = bf16 hi/lo
#define ROWB 80

template<int BM, int OUT>
__global__ __launch_bounds__(256, 2)
void mma_gemm(const __nv_bfloat16* __restrict__ Ah, const __nv_bfloat16* __restrict__ Al,
              const __nv_bfloat16* __restrict__ Bh, const __nv_bfloat16* __restrict__ Bl,
              const float* __restrict__ bias,
              float* __restrict__ Cf,
              __nv_bfloat16* __restrict__ Ch, __nv_bfloat16* __restrict__ Cl,
              int K, int ldc)
{
    constexpr int MT   = BM / 32;              // m16 tiles per warp
    constexpr int ALOFF = BM * ROWB;           // offsets within a stage
    constexpr int BHOFF = 2 * BM * ROWB;
    constexpr int BLOFF = 2 * BM * ROWB + 128 * ROWB;
    constexpr int STG   = (2 * BM + 256) * ROWB;

    extern __shared__ char smem[];
    const uint32_t sb = (uint32_t)__cvta_generic_to_shared(smem);

    const int tid  = threadIdx.x;
    const int wid  = tid >> 5, lane = tid & 31;
    const int wm   = (wid >> 2) * (BM / 2);
    const int wn   = (wid & 3) * 32;
    const int qrow = lane >> 2, qcol = lane & 3;
    const int m0   = blockIdx.y * BM;
    const int n0   = blockIdx.x * 128;

    // ldmatrix lane base offsets
    const uint32_t aoff = (uint32_t)((wm + (lane & 15)) * ROWB + (lane >> 4) * 16);
    const uint32_t boff = (uint32_t)((wn + ((lane >> 4) << 3) + (lane & 7)) * ROWB
                                     + ((lane >> 3) & 1) * 16);

    float acc[MT][4][4];
    #pragma unroll
    for (int i = 0; i < MT; i++)
        #pragma unroll
        for (int j = 0; j < 4; j++)
            #pragma unroll
            for (int q = 0; q < 4; q++) acc[i][j][q] = 0.f;

    auto load_stage = [&](int st, int kc) {
        const uint32_t base = sb + st * STG;
        #pragma unroll
        for (int i = 0; i < BM * 4 / 256; i++) {
            int f = tid + i * 256;
            int row = f >> 2, c = f & 3;
            size_t g = (size_t)(m0 + row) * K + kc + c * 8;
            uint32_t so = (uint32_t)(row * ROWB + c * 16);
            cpasync16(base + so,         Ah + g);
            cpasync16(base + ALOFF + so, Al + g);
        }
        #pragma unroll
        for (int i = 0; i < 2; i++) {
            int f = tid + i * 256;
            int row = f >> 2, c = f & 3;
            size_t g = (size_t)(n0 + row) * K + kc + c * 8;
            uint32_t so = (uint32_t)(row * ROWB + c * 16);
            cpasync16(base + BHOFF + so, Bh + g);
            cpasync16(base + BLOFF + so, Bl + g);
        }
        asm volatile("cp.async.commit_group;\n" ::: "memory");
    };

    const int S = K >> 5;
    load_stage(0, 0);

    for (int s = 0; s < S; s++) {
        if (s + 1 < S) {
            load_stage((s + 1) & 1, (s + 1) * 32);
            asm volatile("cp.async.wait_group 1;\n" ::: "memory");
        } else {
            asm volatile("cp.async.wait_group 0;\n" ::: "memory");
        }
        __syncthreads();

        const uint32_t base = sb + (s & 1) * STG;
        #pragma unroll
        for (int ks = 0; ks < 2; ks++) {
            uint32_t bh[2][4], bl[2][4];
            #pragma unroll
            for (int p = 0; p < 2; p++) {
                ldsm4(bh[p], base + BHOFF + boff + p * (16*ROWB) + ks * 32);
                ldsm4(bl[p], base + BLOFF + boff + p * (16*ROWB) + ks * 32);
            }
            #pragma unroll
            for (int mt = 0; mt < MT; mt++) {
                uint32_t ah[4], al[4];
                ldsm4(ah, base + aoff + mt * (16*ROWB) + ks * 32);
                ldsm4(al, base + ALOFF + aoff + mt * (16*ROWB) + ks * 32);
                #pragma unroll
                for (int nt = 0; nt < 4; nt++) {
                    const uint32_t* bhp = &bh[nt >> 1][(nt & 1) * 2];
                    const uint32_t* blp = &bl[nt >> 1][(nt & 1) * 2];
                    mma16816(acc[mt][nt], ah, bhp);
                    mma16816(acc[mt][nt], al, bhp);
                    mma16816(acc[mt][nt], ah, blp);
                }
            }
        }
        __syncthreads();
    }

    // epilogue
    #pragma unroll
    for (int mt = 0; mt < MT; mt++) {
        int r0 = m0 + wm + mt * 16 + qrow;
        #pragma unroll
        for (int nt = 0; nt < 4; nt++) {
            int c = n0 + wn + nt * 8 + qcol * 2;
            float bv0 = bias[c], bv1 = bias[c + 1];
            float v00 = acc[mt][nt][0] + bv0;
            float v01 = acc[mt][nt][1] + bv1;
            float v10 = acc[mt][nt][2] + bv0;
            float v11 = acc[mt][nt][3] + bv1;
            if (OUT == 1) {
                v00 = fmaxf(v00, 0.f); v01 = fmaxf(v01, 0.f);
                v10 = fmaxf(v10, 0.f); v11 = fmaxf(v11, 0.f);
            }
            if (OUT == 0) {
                size_t i0 = (size_t)r0 * ldc + c;
                size_t i1 = (size_t)(r0 + 8) * ldc + c;
                Cf[i0] = v00; Cf[i0 + 1] = v01;
                Cf[i1] = v10; Cf[i1 + 1] = v11;
            } else {
                __nv_bfloat16 h0, l0, h1, l1;
                size_t i0 = (size_t)r0 * ldc + c;
                bf16_split(v00, h0, l0); bf16_split(v01, h1, l1);
                *(__nv_bfloat162*)(Ch + i0) = __halves2bfloat162(h0, h1);
                *(__nv_bfloat162*)(Cl + i0) = __halves2bfloat162(l0, l1);
                size_t i1 = (size_t)(r0 + 8) * ldc + c;
                bf16_split(v10, h0, l0); bf16_split(v11, h1, l1);
                *(__nv_bfloat162*)(Ch + i1) = __halves2bfloat162(h0, h1);
                *(__nv_bfloat162*)(Cl + i1) = __halves2bfloat162(l0, l1);
            }
        }
    }
}

// ---------------- 4) bbox-size embedding MLP ----------------
__global__ __launch_bounds__(256) void mlp_e_kernel(
    const float* __restrict__ bboxes,
    const float* __restrict__ S1, const float* __restrict__ sb1,
    const float* __restrict__ S2, const float* __restrict__ sb2,
    const float* __restrict__ S3, const float* __restrict__ sb3)
{
    __shared__ float e1[16][64];
    __shared__ float e2[16][256];
    __shared__ float sbh[16], sbw[16];

    const int r0  = blockIdx.x * 16;
    const int tid = threadIdx.x;

    if (tid < 16) {
        const float* bb = bboxes + (size_t)(r0 + tid) * 4;
        sbh[tid] = bb[3] - bb[1];
        sbw[tid] = bb[2] - bb[0];
    }
    __syncthreads();

    for (int i = tid; i < 16*64; i += 256) {
        int row = i >> 6, col = i & 63;
        float v = sbh[row] * S1[col] + sbw[row] * S1[64 + col] + sb1[col];
        e1[row][col] = fmaxf(v, 0.f);
    }
    __syncthreads();

    {
        float a[16];
        const float bv = sb2[tid];
        #pragma unroll
        for (int r = 0; r < 16; r++) a[r] = bv;
        for (int k = 0; k < 64; k++) {
            const float s = S2[(size_t)k * 256 + tid];
            #pragma unroll
            for (int r = 0; r < 16; r++) a[r] += e1[r][k] * s;
        }
        #pragma unroll
        for (int r = 0; r < 16; r++) e2[r][tid] = fmaxf(a[r], 0.f);
    }
    __syncthreads();

    for (int cc = 0; cc < 4; cc++) {
        const int col = tid + cc * 256;
        float a[16];
        const float bv = sb3[col];
        #pragma unroll
        for (int r = 0; r < 16; r++) a[r] = bv;
        for (int k = 0; k < 256; k++) {
            const float s = S3[(size_t)k * 1024 + col];
            #pragma unroll
            for (int r = 0; r < 16; r++) a[r] += e2[r][k] * s;
        }
        #pragma unroll
        for (int r = 0; r < 16; r++) {
            float v = a[r];
            __nv_bfloat16 h, l; bf16_split(v, h, l);
            size_t idx = (size_t)(r0 + r) * 2048 + 1024 + col;
            g_CATh[idx] = h; g_CATl[idx] = l;
        }
    }
}

// ---------------- launch ----------------
extern "C" void kernel_launch(void* const* d_in, const int* in_sizes, int n_in,
                              void* d_out, int out_size)
{
    const float* z      = (const float*)d_in[0];
    const float* bboxes = (const float*)d_in[1];
    const float* W1     = (const float*)d_in[2];
    const float* b1     = (const float*)d_in[3];
    const float* W2     = (const float*)d_in[4];
    const float* b2     = (const float*)d_in[5];
    const float* S1     = (const float*)d_in[6];
    const float* sb1    = (const float*)d_in[7];
    const float* S2     = (const float*)d_in[8];
    const float* sb2    = (const float*)d_in[9];
    const float* S3     = (const float*)d_in[10];
    const float* sb3    = (const float*)d_in[11];
    const float* O      = (const float*)d_in[12];
    const float* ob     = (const float*)d_in[13];
    float* out = (float*)d_out;

    __nv_bfloat16 *Xh, *Xl, *Hh, *Hl, *CATh, *CATl;
    __nv_bfloat16 *W1th, *W1tl, *W2th, *W2tl, *Oth, *Otl;
    cudaGetSymbolAddress((void**)&Xh,   g_Xh);
    cudaGetSymbolAddress((void**)&Xl,   g_Xl);
    cudaGetSymbolAddress((void**)&Hh,   g_Hh);
    cudaGetSymbolAddress((void**)&Hl,   g_Hl);
    cudaGetSymbolAddress((void**)&CATh, g_CATh);
    cudaGetSymbolAddress((void**)&CATl, g_CATl);
    cudaGetSymbolAddress((void**)&W1th, g_W1th);
    cudaGetSymbolAddress((void**)&W1tl, g_W1tl);
    cudaGetSymbolAddress((void**)&W2th, g_W2th);
    cudaGetSymbolAddress((void**)&W2tl, g_W2tl);
    cudaGetSymbolAddress((void**)&Oth,  g_Oth);
    cudaGetSymbolAddress((void**)&Otl,  g_Otl);

    constexpr int SMEM128 = (2*128 + 256) * ROWB * 2;   // 81920
    constexpr int SMEM64  = (2*64  + 256) * ROWB * 2;   // 61440

    static bool attr_set = false;
    if (!attr_set) {
        cudaFuncSetAttribute(mma_gemm<128,1>, cudaFuncAttributeMaxDynamicSharedMemorySize, SMEM128);
        cudaFuncSetAttribute(mma_gemm<64,2>,  cudaFuncAttributeMaxDynamicSharedMemorySize, SMEM64);
        cudaFuncSetAttribute(mma_gemm<64,0>,  cudaFuncAttributeMaxDynamicSharedMemorySize, SMEM64);
        attr_set = true;
    }

    // weight conversion + transpose
    convt_kernel<<<dim3(5120/32, 1280/32), dim3(32, 8)>>>(W1, W1th, W1tl, 1280, 5120);
    convt_kernel<<<dim3(1024/32, 5120/32), dim3(32, 8)>>>(W2, W2th, W2tl, 5120, 1024);
    convt_kernel<<<dim3(1024/32, 2048/32), dim3(32, 8)>>>(O,  Oth,  Otl,  2048, 1024);

    // z NCHW -> NHWC
    transpose_kernel<<<dim3(128, 40, 8), dim3(32, 8)>>>(z);

    // RoIAlign -> X hi/lo
    roi_align_kernel<<<1024, 256>>>(bboxes);

    // bbox MLP -> CAT[:,1024:2048] hi/lo
    mlp_e_kernel<<<64, 256>>>(bboxes, S1, sb1, S2, sb2, S3, sb3);

    // H = relu(X @ W1 + b1)   (1024 x 5120, K=1280)
    mma_gemm<128,1><<<dim3(5120/128, 1024/128), 256, SMEM128>>>(
        Xh, Xl, W1th, W1tl, b1, nullptr, Hh, Hl, 1280, 5120);

    // CAT[:, :1024] = H @ W2 + b2   (1024 x 1024, K=5120)
    mma_gemm<64,2><<<dim3(1024/128, 1024/64), 256, SMEM64>>>(
        Hh, Hl, W2th, W2tl, b2, nullptr, CATh, CATl, 5120, 2048);

    // out = CAT @ O + ob   (1024 x 1024, K=2048)
    mma_gemm<64,0><<<dim3(1024/128, 1024/64), 256, SMEM64>>>(
        CATh, CATl, Oth, Otl, ob, out, nullptr, nullptr, 2048, 1024);
}

// round 5
// speedup vs baseline: 2.0656x; 1.0261x over previous
#include <cuda_runtime.h>
#include <cuda_bf16.h>
#include <cstdint>

#define ROI_SCALE 0.125f

// ---------------- scratch (device globals; no allocation allowed) ----------------
__device__ float g_zt [8ul*64*64*1280];          // NHWC transpose of z
__device__ __nv_bfloat16 g_Xh [1024ul*1280];
__device__ __nv_bfloat16 g_Xl [1024ul*1280];
__device__ __nv_bfloat16 g_Hh [1024ul*5120];
__device__ __nv_bfloat16 g_Hl [1024ul*5120];
__device__ __nv_bfloat16 g_CATh[1024ul*2048];
__device__ __nv_bfloat16 g_CATl[1024ul*2048];
__device__ __nv_bfloat16 g_W1th[5120ul*1280];
__device__ __nv_bfloat16 g_W1tl[5120ul*1280];
__device__ __nv_bfloat16 g_W2th[1024ul*5120];
__device__ __nv_bfloat16 g_W2tl[1024ul*5120];
__device__ __nv_bfloat16 g_Oth [1024ul*2048];
__device__ __nv_bfloat16 g_Otl [1024ul*2048];
__device__ float g_P [2ul*1024*1024];            // split-K partials

// ---------------- helpers ----------------
__device__ __forceinline__ void bf16_split(float v, __nv_bfloat16& h, __nv_bfloat16& l) {
    h = __float2bfloat16(v);
    l = __float2bfloat16(v - __bfloat162float(h));
}

__device__ __forceinline__ void cpasync16(uint32_t saddr, const void* gaddr) {
    asm volatile("cp.async.cg.shared.global [%0], [%1], 16;\n" :: "r"(saddr), "l"(gaddr));
}

__device__ __forceinline__ void ldsm4(uint32_t* r, uint32_t a) {
    asm volatile("ldmatrix.sync.aligned.m8n8.x4.shared.b16 {%0,%1,%2,%3}, [%4];"
                 : "=r"(r[0]), "=r"(r[1]), "=r"(r[2]), "=r"(r[3]) : "r"(a));
}

__device__ __forceinline__ void mma16816(float* c, const uint32_t* a, const uint32_t* b) {
    asm volatile(
        "mma.sync.aligned.m16n8k16.row.col.f32.bf16.bf16.f32 "
        "{%0,%1,%2,%3},{%4,%5,%6,%7},{%8,%9},{%0,%1,%2,%3};"
        : "+f"(c[0]), "+f"(c[1]), "+f"(c[2]), "+f"(c[3])
        : "r"(a[0]), "r"(a[1]), "r"(a[2]), "r"(a[3]), "r"(b[0]), "r"(b[1]));
}

// ---------------- 1) transpose z: (8,1280,64,64) -> (8,4096,1280) ----------------
__global__ void transpose_kernel(const float* __restrict__ z)
{
    __shared__ float tile[32][33];
    const int b  = blockIdx.z;
    const int p0 = blockIdx.x * 32;
    const int c0 = blockIdx.y * 32;
    const float* src = z    + (size_t)b * 1280 * 4096;
    float*       dst = g_zt + (size_t)b * 4096 * 1280;
    const int tx = threadIdx.x, ty = threadIdx.y;
    #pragma unroll
    for (int i = 0; i < 4; i++)
        tile[ty + i*8][tx] = src[(size_t)(c0 + ty + i*8) * 4096 + p0 + tx];
    __syncthreads();
    #pragma unroll
    for (int i = 0; i < 4; i++)
        dst[(size_t)(p0 + ty + i*8) * 1280 + c0 + tx] = tile[tx][ty + i*8];
}

// ---------------- 1b) weight convert + transpose ----------------
__global__ void convt_kernel(const float* __restrict__ W,
                             __nv_bfloat16* __restrict__ Th,
                             __nv_bfloat16* __restrict__ Tl, int K, int N)
{
    __shared__ float tile[32][33];
    const int n0 = blockIdx.x * 32;
    const int k0 = blockIdx.y * 32;
    const int tx = threadIdx.x, ty = threadIdx.y;
    #pragma unroll
    for (int i = 0; i < 4; i++)
        tile[ty + i*8][tx] = W[(size_t)(k0 + ty + i*8) * N + n0 + tx];
    __syncthreads();
    #pragma unroll
    for (int i = 0; i < 4; i++) {
        float v = tile[tx][ty + i*8];
        __nv_bfloat16 h, l; bf16_split(v, h, l);
        size_t idx = (size_t)(n0 + ty + i*8) * K + k0 + tx;
        Th[idx] = h; Tl[idx] = l;
    }
}

// ---------------- 2) RoIAlign 1x1 ----------------
__global__ void roi_align_kernel(const float* __restrict__ bboxes)
{
    __shared__ int   syl[8], syh[8], sxl[8], sxh[8];
    __shared__ float sfy[8], sfx[8], smy[8], smx[8];
    __shared__ int   sgh, sgw;
    __shared__ float sinv;

    const int r   = blockIdx.x;
    const int tid = threadIdx.x;

    if (tid == 0) {
        const float* bb = bboxes + (size_t)r * 4;
        float x1 = bb[0]*ROI_SCALE - 0.5f, y1 = bb[1]*ROI_SCALE - 0.5f;
        float x2 = bb[2]*ROI_SCALE - 0.5f, y2 = bb[3]*ROI_SCALE - 0.5f;
        float rw = x2 - x1, rh = y2 - y1;
        float gw = fminf(fmaxf(ceilf(rw), 1.f), 8.f);
        float gh = fminf(fmaxf(ceilf(rh), 1.f), 8.f);
        sgh = (int)gh; sgw = (int)gw;
        sinv = 1.f / (gh * gw);
        for (int i = 0; i < 8; i++) {
            float ys  = y1 + ((float)i + 0.5f) * rh / gh;
            bool  oy  = (ys < -1.f) || (ys > 64.f);
            float cy  = fmaxf(ys, 0.f);
            float ly0 = floorf(cy);
            bool  hcy = (ly0 >= 63.f);
            syl[i] = (int)fminf(ly0, 63.f);
            syh[i] = (int)fminf(ly0 + 1.f, 63.f);
            sfy[i] = hcy ? 0.f : (cy - ly0);
            smy[i] = (i < sgh && !oy) ? 1.f : 0.f;
            float xs  = x1 + ((float)i + 0.5f) * rw / gw;
            bool  ox  = (xs < -1.f) || (xs > 64.f);
            float cx  = fmaxf(xs, 0.f);
            float lx0 = floorf(cx);
            bool  hcx = (lx0 >= 63.f);
            sxl[i] = (int)fminf(lx0, 63.f);
            sxh[i] = (int)fminf(lx0 + 1.f, 63.f);
            sfx[i] = hcx ? 0.f : (cx - lx0);
            smx[i] = (i < sgw && !ox) ? 1.f : 0.f;
        }
    }
    __syncthreads();

    float acc[5] = {0.f, 0.f, 0.f, 0.f, 0.f};
    const int b = r >> 7;
    const float* base = g_zt + (size_t)b * 4096 * 1280 + tid;

    const int GH = sgh, GW = sgw;
    for (int gy = 0; gy < GH; gy++) {
        float my = smy[gy];
        if (my == 0.f) continue;
        const int yl = syl[gy], yh = syh[gy];
        const float fy = sfy[gy];
        for (int gx = 0; gx < GW; gx++) {
            float m = my * smx[gx];
            if (m == 0.f) continue;
            const int xl = sxl[gx], xh = sxh[gx];
            const float fx = sfx[gx];
            const float w00 = m * (1.f - fy) * (1.f - fx);
            const float w01 = m * (1.f - fy) * fx;
            const float w10 = m * fy * (1.f - fx);
            const float w11 = m * fy * fx;
            const float* p00 = base + (size_t)(yl*64 + xl) * 1280;
            const float* p01 = base + (size_t)(yl*64 + xh) * 1280;
            const float* p10 = base + (size_t)(yh*64 + xl) * 1280;
            const float* p11 = base + (size_t)(yh*64 + xh) * 1280;
            #pragma unroll
            for (int k = 0; k < 5; k++) {
                const int off = k * 256;
                acc[k] += w00 * p00[off];
                acc[k] += w01 * p01[off];
                acc[k] += w10 * p10[off];
                acc[k] += w11 * p11[off];
            }
        }
    }
    #pragma unroll
    for (int k = 0; k < 5; k++) {
        float v = acc[k] * sinv;
        __nv_bfloat16 h, l; bf16_split(v, h, l);
        size_t idx = (size_t)r * 1280 + tid + k * 256;
        g_Xh[idx] = h; g_Xl[idx] = l;
    }
}

// ---------------- 3) bf16-split mma.sync GEMM, ldmatrix + BK=32, split-K ----------------
// OUT: 0 = fp32 store + bias, 1 = relu + bf16 hi/lo, 2 = bf16 hi/lo, 3 = fp32 partial (no bias)
#define ROWB 80

template<int BM, int OUT>
__global__ __launch_bounds__(256, 2)
void mma_gemm(const __nv_bfloat16* __restrict__ Ah, const __nv_bfloat16* __restrict__ Al,
              const __nv_bfloat16* __restrict__ Bh, const __nv_bfloat16* __restrict__ Bl,
              const float* __restrict__ bias,
              float* __restrict__ Cf,
              __nv_bfloat16* __restrict__ Ch, __nv_bfloat16* __restrict__ Cl,
              int K, int Klen, int ldc)
{
    constexpr int MT   = BM / 32;
    constexpr int ALOFF = BM * ROWB;
    constexpr int BHOFF = 2 * BM * ROWB;
    constexpr int BLOFF = 2 * BM * ROWB + 128 * ROWB;
    constexpr int STG   = (2 * BM + 256) * ROWB;

    extern __shared__ char smem[];
    const uint32_t sb = (uint32_t)__cvta_generic_to_shared(smem);

    const int tid  = threadIdx.x;
    const int wid  = tid >> 5, lane = tid & 31;
    const int wm   = (wid >> 2) * (BM / 2);
    const int wn   = (wid & 3) * 32;
    const int qrow = lane >> 2, qcol = lane & 3;
    const int m0   = blockIdx.y * BM;
    const int n0   = blockIdx.x * 128;
    const int koff = blockIdx.z * Klen;

    const uint32_t aoff = (uint32_t)((wm + (lane & 15)) * ROWB + (lane >> 4) * 16);
    const uint32_t boff = (uint32_t)((wn + ((lane >> 4) << 3) + (lane & 7)) * ROWB
                                     + ((lane >> 3) & 1) * 16);

    float acc[MT][4][4];
    #pragma unroll
    for (int i = 0; i < MT; i++)
        #pragma unroll
        for (int j = 0; j < 4; j++)
            #pragma unroll
            for (int q = 0; q < 4; q++) acc[i][j][q] = 0.f;

    auto load_stage = [&](int st, int kc) {
        const uint32_t base = sb + st * STG;
        #pragma unroll
        for (int i = 0; i < BM * 4 / 256; i++) {
            int f = tid + i * 256;
            int row = f >> 2, c = f & 3;
            size_t g = (size_t)(m0 + row) * K + koff + kc + c * 8;
            uint32_t so = (uint32_t)(row * ROWB + c * 16);
            cpasync16(base + so,         Ah + g);
            cpasync16(base + ALOFF + so, Al + g);
        }
        #pragma unroll
        for (int i = 0; i < 2; i++) {
            int f = tid + i * 256;
            int row = f >> 2, c = f & 3;
            size_t g = (size_t)(n0 + row) * K + koff + kc + c * 8;
            uint32_t so = (uint32_t)(row * ROWB + c * 16);
            cpasync16(base + BHOFF + so, Bh + g);
            cpasync16(base + BLOFF + so, Bl + g);
        }
        asm volatile("cp.async.commit_group;\n" ::: "memory");
    };

    const int S = Klen >> 5;
    load_stage(0, 0);

    for (int s = 0; s < S; s++) {
        if (s + 1 < S) {
            load_stage((s + 1) & 1, (s + 1) * 32);
            asm volatile("cp.async.wait_group 1;\n" ::: "memory");
        } else {
            asm volatile("cp.async.wait_group 0;\n" ::: "memory");
        }
        __syncthreads();

        const uint32_t base = sb + (s & 1) * STG;
        #pragma unroll
        for (int ks = 0; ks < 2; ks++) {
            uint32_t bh[2][4], bl[2][4];
            #pragma unroll
            for (int p = 0; p < 2; p++) {
                ldsm4(bh[p], base + BHOFF + boff + p * (16*ROWB) + ks * 32);
                ldsm4(bl[p], base + BLOFF + boff + p * (16*ROWB) + ks * 32);
            }
            #pragma unroll
            for (int mt = 0; mt < MT; mt++) {
                uint32_t ah[4], al[4];
                ldsm4(ah, base + aoff + mt * (16*ROWB) + ks * 32);
                ldsm4(al, base + ALOFF + aoff + mt * (16*ROWB) + ks * 32);
                #pragma unroll
                for (int nt = 0; nt < 4; nt++) {
                    const uint32_t* bhp = &bh[nt >> 1][(nt & 1) * 2];
                    const uint32_t* blp = &bl[nt >> 1][(nt & 1) * 2];
                    mma16816(acc[mt][nt], ah, bhp);
                    mma16816(acc[mt][nt], al, bhp);
                    mma16816(acc[mt][nt], ah, blp);
                }
            }
        }
        __syncthreads();
    }

    float* Cfz = (OUT == 3) ? (Cf + (size_t)blockIdx.z * 1024 * 1024) : Cf;

    #pragma unroll
    for (int mt = 0; mt < MT; mt++) {
        int r0 = m0 + wm + mt * 16 + qrow;
        #pragma unroll
        for (int nt = 0; nt < 4; nt++) {
            int c = n0 + wn + nt * 8 + qcol * 2;
            float bv0 = (OUT == 3) ? 0.f : bias[c];
            float bv1 = (OUT == 3) ? 0.f : bias[c + 1];
            float v00 = acc[mt][nt][0] + bv0;
            float v01 = acc[mt][nt][1] + bv1;
            float v10 = acc[mt][nt][2] + bv0;
            float v11 = acc[mt][nt][3] + bv1;
            if (OUT == 1) {
                v00 = fmaxf(v00, 0.f); v01 = fmaxf(v01, 0.f);
                v10 = fmaxf(v10, 0.f); v11 = fmaxf(v11, 0.f);
            }
            if (OUT == 0 || OUT == 3) {
                size_t i0 = (size_t)r0 * ldc + c;
                size_t i1 = (size_t)(r0 + 8) * ldc + c;
                Cfz[i0] = v00; Cfz[i0 + 1] = v01;
                Cfz[i1] = v10; Cfz[i1 + 1] = v11;
            } else {
                __nv_bfloat16 h0, l0, h1, l1;
                size_t i0 = (size_t)r0 * ldc + c;
                bf16_split(v00, h0, l0); bf16_split(v01, h1, l1);
                *(__nv_bfloat162*)(Ch + i0) = __halves2bfloat162(h0, h1);
                *(__nv_bfloat162*)(Cl + i0) = __halves2bfloat162(l0, l1);
                size_t i1 = (size_t)(r0 + 8) * ldc + c;
                bf16_split(v10, h0, l0); bf16_split(v11, h1, l1);
                *(__nv_bfloat162*)(Ch + i1) = __halves2bfloat162(h0, h1);
                *(__nv_bfloat162*)(Cl + i1) = __halves2bfloat162(l0, l1);
            }
        }
    }
}

// ---------------- 3b) split-K reduce ----------------
// OUT: 2 = bf16 hi/lo to CAT (ldc 2048), 0 = f32 to out (ldc 1024)
template<int OUT>
__global__ __launch_bounds__(256)
void reduce_k(const float* __restrict__ P, const float* __restrict__ bias,
              float* __restrict__ Cf,
              __nv_bfloat16* __restrict__ Ch, __nv_bfloat16* __restrict__ Cl, int ldc)
{
    const int idx = blockIdx.x * 256 + threadIdx.x;   // f4 index
    const int r   = idx >> 8;
    const int c   = (idx & 255) * 4;
    const size_t p = (size_t)r * 1024 + c;
    float4 a = *(const float4*)(P + p);
    float4 b = *(const float4*)(P + 1024ul*1024 + p);
    float4 bv = *(const float4*)(bias + c);
    float v0 = a.x + b.x + bv.x;
    float v1 = a.y + b.y + bv.y;
    float v2 = a.z + b.z + bv.z;
    float v3 = a.w + b.w + bv.w;
    if (OUT == 0) {
        *(float4*)(Cf + (size_t)r * ldc + c) = make_float4(v0, v1, v2, v3);
    } else {
        __nv_bfloat16 h0,l0,h1,l1,h2,l2,h3,l3;
        bf16_split(v0,h0,l0); bf16_split(v1,h1,l1);
        bf16_split(v2,h2,l2); bf16_split(v3,h3,l3);
        size_t o = (size_t)r * ldc + c;
        *(__nv_bfloat162*)(Ch + o)     = __halves2bfloat162(h0, h1);
        *(__nv_bfloat162*)(Ch + o + 2) = __halves2bfloat162(h2, h3);
        *(__nv_bfloat162*)(Cl + o)     = __halves2bfloat162(l0, l1);
        *(__nv_bfloat162*)(Cl + o + 2) = __halves2bfloat162(l2, l3);
    }
}

// ---------------- 4) bbox-size embedding MLP ----------------
__global__ __launch_bounds__(256) void mlp_e_kernel(
    const float* __restrict__ bboxes,
    const float* __restrict__ S1, const float* __restrict__ sb1,
    const float* __restrict__ S2, const float* __restrict__ sb2,
    const float* __restrict__ S3, const float* __restrict__ sb3)
{
    __shared__ float e1[16][64];
    __shared__ float e2[16][256];
    __shared__ float sbh[16], sbw[16];

    const int r0  = blockIdx.x * 16;
    const int tid = threadIdx.x;

    if (tid < 16) {
        const float* bb = bboxes + (size_t)(r0 + tid) * 4;
        sbh[tid] = bb[3] - bb[1];
        sbw[tid] = bb[2] - bb[0];
    }
    __syncthreads();

    for (int i = tid; i < 16*64; i += 256) {
        int row = i >> 6, col = i & 63;
        float v = sbh[row] * S1[col] + sbw[row] * S1[64 + col] + sb1[col];
        e1[row][col] = fmaxf(v, 0.f);
    }
    __syncthreads();

    {
        float a[16];
        const float bv = sb2[tid];
        #pragma unroll
        for (int r = 0; r < 16; r++) a[r] = bv;
        for (int k = 0; k < 64; k++) {
            const float s = S2[(size_t)k * 256 + tid];
            #pragma unroll
            for (int r = 0; r < 16; r++) a[r] += e1[r][k] * s;
        }
        #pragma unroll
        for (int r = 0; r < 16; r++) e2[r][tid] = fmaxf(a[r], 0.f);
    }
    __syncthreads();

    for (int cc = 0; cc < 4; cc++) {
        const int col = tid + cc * 256;
        float a[16];
        const float bv = sb3[col];
        #pragma unroll
        for (int r = 0; r < 16; r++) a[r] = bv;
        for (int k = 0; k < 256; k++) {
            const float s = S3[(size_t)k * 1024 + col];
            #pragma unroll
            for (int r = 0; r < 16; r++) a[r] += e2[r][k] * s;
        }
        #pragma unroll
        for (int r = 0; r < 16; r++) {
            float v = a[r];
            __nv_bfloat16 h, l; bf16_split(v, h, l);
            size_t idx = (size_t)(r0 + r) * 2048 + 1024 + col;
            g_CATh[idx] = h; g_CATl[idx] = l;
        }
    }
}

// ---------------- launch ----------------
extern "C" void kernel_launch(void* const* d_in, const int* in_sizes, int n_in,
                              void* d_out, int out_size)
{
    const float* z      = (const float*)d_in[0];
    const float* bboxes = (const float*)d_in[1];
    const float* W1     = (const float*)d_in[2];
    const float* b1     = (const float*)d_in[3];
    const float* W2     = (const float*)d_in[4];
    const float* b2     = (const float*)d_in[5];
    const float* S1     = (const float*)d_in[6];
    const float* sb1    = (const float*)d_in[7];
    const float* S2     = (const float*)d_in[8];
    const float* sb2    = (const float*)d_in[9];
    const float* S3     = (const float*)d_in[10];
    const float* sb3    = (const float*)d_in[11];
    const float* O      = (const float*)d_in[12];
    const float* ob     = (const float*)d_in[13];
    float* out = (float*)d_out;

    __nv_bfloat16 *Xh, *Xl, *Hh, *Hl, *CATh, *CATl;
    __nv_bfloat16 *W1th, *W1tl, *W2th, *W2tl, *Oth, *Otl;
    float* P;
    cudaGetSymbolAddress((void**)&Xh,   g_Xh);
    cudaGetSymbolAddress((void**)&Xl,   g_Xl);
    cudaGetSymbolAddress((void**)&Hh,   g_Hh);
    cudaGetSymbolAddress((void**)&Hl,   g_Hl);
    cudaGetSymbolAddress((void**)&CATh, g_CATh);
    cudaGetSymbolAddress((void**)&CATl, g_CATl);
    cudaGetSymbolAddress((void**)&W1th, g_W1th);
    cudaGetSymbolAddress((void**)&W1tl, g_W1tl);
    cudaGetSymbolAddress((void**)&W2th, g_W2th);
    cudaGetSymbolAddress((void**)&W2tl, g_W2tl);
    cudaGetSymbolAddress((void**)&Oth,  g_Oth);
    cudaGetSymbolAddress((void**)&Otl,  g_Otl);
    cudaGetSymbolAddress((void**)&P,    g_P);

    constexpr int SMEM128 = (2*128 + 256) * ROWB * 2;   // 81920

    static bool attr_set = false;
    if (!attr_set) {
        cudaFuncSetAttribute(mma_gemm<128,1>, cudaFuncAttributeMaxDynamicSharedMemorySize, SMEM128);
        cudaFuncSetAttribute(mma_gemm<128,3>, cudaFuncAttributeMaxDynamicSharedMemorySize, SMEM128);
        attr_set = true;
    }

    // weight conversion + transpose
    convt_kernel<<<dim3(5120/32, 1280/32), dim3(32, 8)>>>(W1, W1th, W1tl, 1280, 5120);
    convt_kernel<<<dim3(1024/32, 5120/32), dim3(32, 8)>>>(W2, W2th, W2tl, 5120, 1024);
    convt_kernel<<<dim3(1024/32, 2048/32), dim3(32, 8)>>>(O,  Oth,  Otl,  2048, 1024);

    // z NCHW -> NHWC
    transpose_kernel<<<dim3(128, 40, 8), dim3(32, 8)>>>(z);

    // RoIAlign -> X hi/lo
    roi_align_kernel<<<1024, 256>>>(bboxes);

    // bbox MLP -> CAT[:,1024:2048] hi/lo
    mlp_e_kernel<<<64, 256>>>(bboxes, S1, sb1, S2, sb2, S3, sb3);

    // H = relu(X @ W1 + b1)   (1024 x 5120, K=1280)
    mma_gemm<128,1><<<dim3(5120/128, 1024/128), 256, SMEM128>>>(
        Xh, Xl, W1th, W1tl, b1, nullptr, Hh, Hl, 1280, 1280, 5120);

    // P = H @ W2 (split-K 2x2560), then CAT[:, :1024] = bf16split(P0+P1+b2)
    mma_gemm<128,3><<<dim3(1024/128, 1024/128, 2), 256, SMEM128>>>(
        Hh, Hl, W2th, W2tl, nullptr, P, nullptr, nullptr, 5120, 2560, 1024);
    reduce_k<2><<<1024, 256>>>(P, b2, nullptr, CATh, CATl, 2048);

    // P = CAT @ O (split-K 2x1024), then out = P0+P1+ob
    mma_gemm<128,3><<<dim3(1024/128, 1024/128, 2), 256, SMEM128>>>(
        CATh, CATl, Oth, Otl, nullptr, P, nullptr, nullptr, 2048, 1024, 1024);
    reduce_k<0><<<1024, 256>>>(P, ob, out, nullptr, nullptr, 1024);
}

// round 6
// speedup vs baseline: 2.3752x; 1.1499x over previous
#include <cuda_runtime.h>
#include <cuda_fp16.h>
#include <cstdint>

#define ROI_SCALE 0.125f

// ---------------- scratch (device globals; no allocation allowed) ----------------
__device__ float g_zt [8ul*64*64*1280];   // NHWC transpose of z
__device__ __half g_Xh [1024ul*1280];
__device__ __half g_Xl [1024ul*1280];
__device__ __half g_Hh [1024ul*5120];
__device__ __half g_Hl [1024ul*5120];
__device__ __half g_CATh[1024ul*2048];
__device__ __half g_CATl[1024ul*2048];
__device__ __half g_W1t[5120ul*1280];     // N-major fp16 weights (single precision-level)
__device__ __half g_W2t[1024ul*5120];
__device__ __half g_Ot [1024ul*2048];
__device__ float g_P [2ul*1024*1024];     // split-K partials

// ---------------- helpers ----------------
__device__ __forceinline__ void fp16_split(float v, __half& h, __half& l) {
    h = __float2half_rn(v);
    l = __float2half_rn(v - __half2float(h));
}

__device__ __forceinline__ void cpasync16(uint32_t saddr, const void* gaddr) {
    asm volatile("cp.async.cg.shared.global [%0], [%1], 16;\n" :: "r"(saddr), "l"(gaddr));
}

__device__ __forceinline__ void ldsm4(uint32_t* r, uint32_t a) {
    asm volatile("ldmatrix.sync.aligned.m8n8.x4.shared.b16 {%0,%1,%2,%3}, [%4];"
                 : "=r"(r[0]), "=r"(r[1]), "=r"(r[2]), "=r"(r[3]) : "r"(a));
}

__device__ __forceinline__ void mma16816(float* c, const uint32_t* a, const uint32_t* b) {
    asm volatile(
        "mma.sync.aligned.m16n8k16.row.col.f32.f16.f16.f32 "
        "{%0,%1,%2,%3},{%4,%5,%6,%7},{%8,%9},{%0,%1,%2,%3};"
        : "+f"(c[0]), "+f"(c[1]), "+f"(c[2]), "+f"(c[3])
        : "r"(a[0]), "r"(a[1]), "r"(a[2]), "r"(a[3]), "r"(b[0]), "r"(b[1]));
}

// ---------------- 1) transpose z: (8,1280,64,64) -> (8,4096,1280) ----------------
__global__ void transpose_kernel(const float* __restrict__ z)
{
    __shared__ float tile[32][33];
    const int b  = blockIdx.z;
    const int p0 = blockIdx.x * 32;
    const int c0 = blockIdx.y * 32;
    const float* src = z    + (size_t)b * 1280 * 4096;
    float*       dst = g_zt + (size_t)b * 4096 * 1280;
    const int tx = threadIdx.x, ty = threadIdx.y;
    #pragma unroll
    for (int i = 0; i < 4; i++)
        tile[ty + i*8][tx] = src[(size_t)(c0 + ty + i*8) * 4096 + p0 + tx];
    __syncthreads();
    #pragma unroll
    for (int i = 0; i < 4; i++)
        dst[(size_t)(p0 + ty + i*8) * 1280 + c0 + tx] = tile[tx][ty + i*8];
}

// ---------------- 1b) weight convert + transpose: W[K][N] f32 -> Wt[N][K] fp16 ----
__global__ void convt_kernel(const float* __restrict__ W,
                             __half* __restrict__ T, int K, int N)
{
    __shared__ float tile[32][33];
    const int n0 = blockIdx.x * 32;
    const int k0 = blockIdx.y * 32;
    const int tx = threadIdx.x, ty = threadIdx.y;
    #pragma unroll
    for (int i = 0; i < 4; i++)
        tile[ty + i*8][tx] = W[(size_t)(k0 + ty + i*8) * N + n0 + tx];
    __syncthreads();
    #pragma unroll
    for (int i = 0; i < 4; i++) {
        float v = tile[tx][ty + i*8];
        T[(size_t)(n0 + ty + i*8) * K + k0 + tx] = __float2half_rn(v);
    }
}

// ---------------- 2) RoIAlign 1x1, separable weights ----------------
__global__ void roi_align_kernel(const float* __restrict__ bboxes)
{
    __shared__ int   syi[18], sxi[18];
    __shared__ float syw[18], sxw[18];
    __shared__ int   sny, snx;
    __shared__ float sinv;

    const int r   = blockIdx.x;
    const int tid = threadIdx.x;

    if (tid == 0) {
        const float* bb = bboxes + (size_t)r * 4;
        float x1 = bb[0]*ROI_SCALE - 0.5f, y1 = bb[1]*ROI_SCALE - 0.5f;
        float x2 = bb[2]*ROI_SCALE - 0.5f, y2 = bb[3]*ROI_SCALE - 0.5f;
        float rw = x2 - x1, rh = y2 - y1;
        float gwf = fminf(fmaxf(ceilf(rw), 1.f), 8.f);
        float ghf = fminf(fmaxf(ceilf(rh), 1.f), 8.f);
        int gh = (int)ghf, gw = (int)gwf;
        sinv = 1.f / (ghf * gwf);

        float W[64];
        // --- y axis ---
        for (int j = 0; j < 64; j++) W[j] = 0.f;
        for (int i = 0; i < gh; i++) {
            float ys = y1 + ((float)i + 0.5f) * rh / ghf;
            if (ys < -1.f || ys > 64.f) continue;
            float cy = fmaxf(ys, 0.f);
            float l0 = floorf(cy);
            int yl = (int)fminf(l0, 63.f);
            int yh = (int)fminf(l0 + 1.f, 63.f);
            float fy = (l0 >= 63.f) ? 0.f : (cy - l0);
            W[yl] += 1.f - fy;
            W[yh] += fy;
        }
        int n = 0;
        for (int j = 0; j < 64; j++)
            if (W[j] != 0.f) { syi[n] = j; syw[n] = W[j]; n++; }
        sny = n;
        // --- x axis ---
        for (int j = 0; j < 64; j++) W[j] = 0.f;
        for (int i = 0; i < gw; i++) {
            float xs = x1 + ((float)i + 0.5f) * rw / gwf;
            if (xs < -1.f || xs > 64.f) continue;
            float cx = fmaxf(xs, 0.f);
            float l0 = floorf(cx);
            int xl = (int)fminf(l0, 63.f);
            int xh = (int)fminf(l0 + 1.f, 63.f);
            float fx = (l0 >= 63.f) ? 0.f : (cx - l0);
            W[xl] += 1.f - fx;
            W[xh] += fx;
        }
        n = 0;
        for (int j = 0; j < 64; j++)
            if (W[j] != 0.f) { sxi[n] = j; sxw[n] = W[j]; n++; }
        snx = n;
    }
    __syncthreads();

    const int b = r >> 7;
    const float* base = g_zt + (size_t)b * 4096 * 1280 + tid;
    float acc[5] = {0.f, 0.f, 0.f, 0.f, 0.f};

    const int NY = sny, NX = snx;
    for (int iy = 0; iy < NY; iy++) {
        const float* py = base + (size_t)syi[iy] * (64 * 1280);
        float t[5] = {0.f, 0.f, 0.f, 0.f, 0.f};
        for (int ix = 0; ix < NX; ix++) {
            const float* p = py + (size_t)sxi[ix] * 1280;
            const float w = sxw[ix];
            #pragma unroll
            for (int k = 0; k < 5; k++) t[k] += w * p[k * 256];
        }
        const float wy = syw[iy];
        #pragma unroll
        for (int k = 0; k < 5; k++) acc[k] += wy * t[k];
    }
    #pragma unroll
    for (int k = 0; k < 5; k++) {
        float v = acc[k] * sinv;
        __half h, l; fp16_split(v, h, l);
        size_t idx = (size_t)r * 1280 + tid + k * 256;
        g_Xh[idx] = h; g_Xl[idx] = l;
    }
}

// ---------------- 3) fp16 split-2 mma.sync GEMM, ldmatrix + BK=32, 3-stage ----------------
// C = [relu](A @ B + bias). A = Ah + Al (fp16 hi/lo, row-major), B single fp16 N-major.
// CTA tile 128x128, 8 warps 2(m) x 4(n), warp tile 64x32.
// OUT: 1 = relu + fp16 hi/lo store, 3 = fp32 split-K partial (no bias)
#define ROWB 80
#define GBM 128

template<int OUT>
__global__ __launch_bounds__(256, 2)
void mma_gemm(const __half* __restrict__ Ah, const __half* __restrict__ Al,
              const __half* __restrict__ Bh,
              const float* __restrict__ bias,
              float* __restrict__ Cf,
              __half* __restrict__ Ch, __half* __restrict__ Cl,
              int K, int Klen, int ldc)
{
    constexpr int ALOFF = GBM * ROWB;
    constexpr int BHOFF = 2 * GBM * ROWB;
    constexpr int STG   = (2 * GBM + 128) * ROWB;   // 30720 B

    extern __shared__ char smem[];
    const uint32_t sb = (uint32_t)__cvta_generic_to_shared(smem);

    const int tid  = threadIdx.x;
    const int wid  = tid >> 5, lane = tid & 31;
    const int wm   = (wid >> 2) * 64;
    const int wn   = (wid & 3) * 32;
    const int qrow = lane >> 2, qcol = lane & 3;
    const int m0   = blockIdx.y * GBM;
    const int n0   = blockIdx.x * 128;
    const int koff = blockIdx.z * Klen;

    const uint32_t aoff = (uint32_t)((wm + (lane & 15)) * ROWB + (lane >> 4) * 16);
    const uint32_t boff = (uint32_t)((wn + ((lane >> 4) << 3) + (lane & 7)) * ROWB
                                     + ((lane >> 3) & 1) * 16);

    float acc[4][4][4];
    #pragma unroll
    for (int i = 0; i < 4; i++)
        #pragma unroll
        for (int j = 0; j < 4; j++)
            #pragma unroll
            for (int q = 0; q < 4; q++) acc[i][j][q] = 0.f;

    auto load_stage = [&](int st, int kc) {
        const uint32_t base = sb + st * STG;
        #pragma unroll
        for (int i = 0; i < 2; i++) {
            int f = tid + i * 256;
            int row = f >> 2, c = f & 3;
            size_t g = (size_t)(m0 + row) * K + koff + kc + c * 8;
            uint32_t so = (uint32_t)(row * ROWB + c * 16);
            cpasync16(base + so,         Ah + g);
            cpasync16(base + ALOFF + so, Al + g);
        }
        #pragma unroll
        for (int i = 0; i < 2; i++) {
            int f = tid + i * 256;
            int row = f >> 2, c = f & 3;
            size_t g = (size_t)(n0 + row) * K + koff + kc + c * 8;
            uint32_t so = (uint32_t)(row * ROWB + c * 16);
            cpasync16(base + BHOFF + so, Bh + g);
        }
        asm volatile("cp.async.commit_group;\n" ::: "memory");
    };

    const int S = Klen >> 5;
    load_stage(0, 0);
    load_stage(1, 32);

    for (int s = 0; s < S; s++) {
        if (s + 2 < S) {
            asm volatile("cp.async.wait_group 1;\n" ::: "memory");
        } else {
            asm volatile("cp.async.wait_group 0;\n" ::: "memory");
        }
        __syncthreads();
        if (s + 2 < S) load_stage((s + 2) % 3, (s + 2) * 32);

        const uint32_t base = sb + (s % 3) * STG;
        #pragma unroll
        for (int ks = 0; ks < 2; ks++) {
            uint32_t bh[2][4];
            #pragma unroll
            for (int p = 0; p < 2; p++)
                ldsm4(bh[p], base + BHOFF + boff + p * (16*ROWB) + ks * 32);
            #pragma unroll
            for (int mt = 0; mt < 4; mt++) {
                uint32_t ah[4], al[4];
                ldsm4(ah, base + aoff + mt * (16*ROWB) + ks * 32);
                ldsm4(al, base + ALOFF + aoff + mt * (16*ROWB) + ks * 32);
                #pragma unroll
                for (int nt = 0; nt < 4; nt++) {
                    const uint32_t* bp = &bh[nt >> 1][(nt & 1) * 2];
                    mma16816(acc[mt][nt], ah, bp);
                    mma16816(acc[mt][nt], al, bp);
                }
            }
        }
        __syncthreads();
    }

    float* Cfz = (OUT == 3) ? (Cf + (size_t)blockIdx.z * 1024 * 1024) : Cf;

    #pragma unroll
    for (int mt = 0; mt < 4; mt++) {
        int r0 = m0 + wm + mt * 16 + qrow;
        #pragma unroll
        for (int nt = 0; nt < 4; nt++) {
            int c = n0 + wn + nt * 8 + qcol * 2;
            float bv0 = (OUT == 3) ? 0.f : bias[c];
            float bv1 = (OUT == 3) ? 0.f : bias[c + 1];
            float v00 = acc[mt][nt][0] + bv0;
            float v01 = acc[mt][nt][1] + bv1;
            float v10 = acc[mt][nt][2] + bv0;
            float v11 = acc[mt][nt][3] + bv1;
            if (OUT == 1) {
                v00 = fmaxf(v00, 0.f); v01 = fmaxf(v01, 0.f);
                v10 = fmaxf(v10, 0.f); v11 = fmaxf(v11, 0.f);
                __half h0, l0, h1, l1;
                size_t i0 = (size_t)r0 * ldc + c;
                fp16_split(v00, h0, l0); fp16_split(v01, h1, l1);
                *(__half2*)(Ch + i0) = __halves2half2(h0, h1);
                *(__half2*)(Cl + i0) = __halves2half2(l0, l1);
                size_t i1 = (size_t)(r0 + 8) * ldc + c;
                fp16_split(v10, h0, l0); fp16_split(v11, h1, l1);
                *(__half2*)(Ch + i1) = __halves2half2(h0, h1);
                *(__half2*)(Cl + i1) = __halves2half2(l0, l1);
            } else {
                size_t i0 = (size_t)r0 * ldc + c;
                size_t i1 = (size_t)(r0 + 8) * ldc + c;
                Cfz[i0] = v00; Cfz[i0 + 1] = v01;
                Cfz[i1] = v10; Cfz[i1 + 1] = v11;
            }
        }
    }
}

// ---------------- 3b) split-K reduce ----------------
// OUT: 2 = fp16 hi/lo to CAT (ldc 2048), 0 = f32 to out (ldc 1024)
template<int OUT>
__global__ __launch_bounds__(256)
void reduce_k(const float* __restrict__ P, const float* __restrict__ bias,
              float* __restrict__ Cf,
              __half* __restrict__ Ch, __half* __restrict__ Cl, int ldc)
{
    const int idx = blockIdx.x * 256 + threadIdx.x;   // f4 index
    const int r   = idx >> 8;
    const int c   = (idx & 255) * 4;
    const size_t p = (size_t)r * 1024 + c;
    float4 a = *(const float4*)(P + p);
    float4 b = *(const float4*)(P + 1024ul*1024 + p);
    float4 bv = *(const float4*)(bias + c);
    float v0 = a.x + b.x + bv.x;
    float v1 = a.y + b.y + bv.y;
    float v2 = a.z + b.z + bv.z;
    float v3 = a.w + b.w + bv.w;
    if (OUT == 0) {
        *(float4*)(Cf + (size_t)r * ldc + c) = make_float4(v0, v1, v2, v3);
    } else {
        __half h0,l0,h1,l1,h2,l2,h3,l3;
        fp16_split(v0,h0,l0); fp16_split(v1,h1,l1);
        fp16_split(v2,h2,l2); fp16_split(v3,h3,l3);
        size_t o = (size_t)r * ldc + c;
        *(__half2*)(Ch + o)     = __halves2half2(h0, h1);
        *(__half2*)(Ch + o + 2) = __halves2half2(h2, h3);
        *(__half2*)(Cl + o)     = __halves2half2(l0, l1);
        *(__half2*)(Cl + o + 2) = __halves2half2(l2, l3);
    }
}

// ---------------- 4) bbox-size embedding MLP ----------------
__global__ __launch_bounds__(256) void mlp_e_kernel(
    const float* __restrict__ bboxes,
    const float* __restrict__ S1, const float* __restrict__ sb1,
    const float* __restrict__ S2, const float* __restrict__ sb2,
    const float* __restrict__ S3, const float* __restrict__ sb3)
{
    __shared__ float e1[16][64];
    __shared__ float e2[16][256];
    __shared__ float sbh[16], sbw[16];

    const int r0  = blockIdx.x * 16;
    const int tid = threadIdx.x;

    if (tid < 16) {
        const float* bb = bboxes + (size_t)(r0 + tid) * 4;
        sbh[tid] = bb[3] - bb[1];
        sbw[tid] = bb[2] - bb[0];
    }
    __syncthreads();

    for (int i = tid; i < 16*64; i += 256) {
        int row = i >> 6, col = i & 63;
        float v = sbh[row] * S1[col] + sbw[row] * S1[64 + col] + sb1[col];
        e1[row][col] = fmaxf(v, 0.f);
    }
    __syncthreads();

    {
        float a[16];
        const float bv = sb2[tid];
        #pragma unroll
        for (int r = 0; r < 16; r++) a[r] = bv;
        for (int k = 0; k < 64; k++) {
            const float s = S2[(size_t)k * 256 + tid];
            #pragma unroll
            for (int r = 0; r < 16; r++) a[r] += e1[r][k] * s;
        }
        #pragma unroll
        for (int r = 0; r < 16; r++) e2[r][tid] = fmaxf(a[r], 0.f);
    }
    __syncthreads();

    for (int cc = 0; cc < 4; cc++) {
        const int col = tid + cc * 256;
        float a[16];
        const float bv = sb3[col];
        #pragma unroll
        for (int r = 0; r < 16; r++) a[r] = bv;
        for (int k = 0; k < 256; k++) {
            const float s = S3[(size_t)k * 1024 + col];
            #pragma unroll
            for (int r = 0; r < 16; r++) a[r] += e2[r][k] * s;
        }
        #pragma unroll
        for (int r = 0; r < 16; r++) {
            float v = a[r];
            __half h, l; fp16_split(v, h, l);
            size_t idx = (size_t)(r0 + r) * 2048 + 1024 + col;
            g_CATh[idx] = h; g_CATl[idx] = l;
        }
    }
}

// ---------------- launch ----------------
extern "C" void kernel_launch(void* const* d_in, const int* in_sizes, int n_in,
                              void* d_out, int out_size)
{
    const float* z      = (const float*)d_in[0];
    const float* bboxes = (const float*)d_in[1];
    const float* W1     = (const float*)d_in[2];
    const float* b1     = (const float*)d_in[3];
    const float* W2     = (const float*)d_in[4];
    const float* b2     = (const float*)d_in[5];
    const float* S1     = (const float*)d_in[6];
    const float* sb1    = (const float*)d_in[7];
    const float* S2     = (const float*)d_in[8];
    const float* sb2    = (const float*)d_in[9];
    const float* S3     = (const float*)d_in[10];
    const float* sb3    = (const float*)d_in[11];
    const float* O      = (const float*)d_in[12];
    const float* ob     = (const float*)d_in[13];
    float* out = (float*)d_out;

    __half *Xh, *Xl, *Hh, *Hl, *CATh, *CATl, *W1t, *W2t, *Ot;
    float* P;
    cudaGetSymbolAddress((void**)&Xh,   g_Xh);
    cudaGetSymbolAddress((void**)&Xl,   g_Xl);
    cudaGetSymbolAddress((void**)&Hh,   g_Hh);
    cudaGetSymbolAddress((void**)&Hl,   g_Hl);
    cudaGetSymbolAddress((void**)&CATh, g_CATh);
    cudaGetSymbolAddress((void**)&CATl, g_CATl);
    cudaGetSymbolAddress((void**)&W1t,  g_W1t);
    cudaGetSymbolAddress((void**)&W2t,  g_W2t);
    cudaGetSymbolAddress((void**)&Ot,   g_Ot);
    cudaGetSymbolAddress((void**)&P,    g_P);

    constexpr int SMEM = (2*GBM + 128) * ROWB * 3;   // 92160

    static bool attr_set = false;
    if (!attr_set) {
        cudaFuncSetAttribute(mma_gemm<1>, cudaFuncAttributeMaxDynamicSharedMemorySize, SMEM);
        cudaFuncSetAttribute(mma_gemm<3>, cudaFuncAttributeMaxDynamicSharedMemorySize, SMEM);
        attr_set = true;
    }

    // weight conversion + transpose (fp16)
    convt_kernel<<<dim3(5120/32, 1280/32), dim3(32, 8)>>>(W1, W1t, 1280, 5120);
    convt_kernel<<<dim3(1024/32, 5120/32), dim3(32, 8)>>>(W2, W2t, 5120, 1024);
    convt_kernel<<<dim3(1024/32, 2048/32), dim3(32, 8)>>>(O,  Ot,  2048, 1024);

    // z NCHW -> NHWC
    transpose_kernel<<<dim3(128, 40, 8), dim3(32, 8)>>>(z);

    // RoIAlign -> X hi/lo (separable)
    roi_align_kernel<<<1024, 256>>>(bboxes);

    // bbox MLP -> CAT[:,1024:2048] hi/lo
    mlp_e_kernel<<<64, 256>>>(bboxes, S1, sb1, S2, sb2, S3, sb3);

    // H = relu(X @ W1 + b1)   (1024 x 5120, K=1280)
    mma_gemm<1><<<dim3(5120/128, 1024/128), 256, SMEM>>>(
        Xh, Xl, W1t, b1, nullptr, Hh, Hl, 1280, 1280, 5120);

    // P = H @ W2 (split-K 2x2560), then CAT[:, :1024] = fp16split(P0+P1+b2)
    mma_gemm<3><<<dim3(1024/128, 1024/128, 2), 256, SMEM>>>(
        Hh, Hl, W2t, nullptr, P, nullptr, nullptr, 5120, 2560, 1024);
    reduce_k<2><<<1024, 256>>>(P, b2, nullptr, CATh, CATl, 2048);

    // P = CAT @ O (split-K 2x1024), then out = P0+P1+ob
    mma_gemm<3><<<dim3(1024/128, 1024/128, 2), 256, SMEM>>>(
        CATh, CATl, Ot, nullptr, P, nullptr, nullptr, 2048, 1024, 1024);
    reduce_k<0><<<1024, 256>>>(P, ob, out, nullptr, nullptr, 1024);
}

// round 7
// speedup vs baseline: 2.5532x; 1.0749x over previous
#include <cuda_runtime.h>
#include <cuda_fp16.h>
#include <cstdint>

#define ROI_SCALE 0.125f

// ---------------- scratch (device globals; no allocation allowed) ----------------
__device__ float g_zt [8ul*64*64*1280];   // NHWC transpose of z
__device__ __half g_Xh [1024ul*1280];
__device__ __half g_Xl [1024ul*1280];
__device__ __half g_H  [1024ul*5120];     // fp16 activations (single)
__device__ __half g_CAT[1024ul*2048];     // fp16 concat (single)
__device__ __half g_W1t[5120ul*1280];     // N-major fp16 weights
__device__ __half g_W2t[1024ul*5120];
__device__ __half g_Ot [1024ul*2048];
__device__ float g_P [2ul*1024*1024];     // split-K partials

// ---------------- helpers ----------------
__device__ __forceinline__ void fp16_split(float v, __half& h, __half& l) {
    h = __float2half_rn(v);
    l = __float2half_rn(v - __half2float(h));
}

__device__ __forceinline__ void cpasync16(uint32_t saddr, const void* gaddr) {
    asm volatile("cp.async.cg.shared.global [%0], [%1], 16;\n" :: "r"(saddr), "l"(gaddr));
}

__device__ __forceinline__ void ldsm4(uint32_t* r, uint32_t a) {
    asm volatile("ldmatrix.sync.aligned.m8n8.x4.shared.b16 {%0,%1,%2,%3}, [%4];"
                 : "=r"(r[0]), "=r"(r[1]), "=r"(r[2]), "=r"(r[3]) : "r"(a));
}

__device__ __forceinline__ void mma16816(float* c, const uint32_t* a, const uint32_t* b) {
    asm volatile(
        "mma.sync.aligned.m16n8k16.row.col.f32.f16.f16.f32 "
        "{%0,%1,%2,%3},{%4,%5,%6,%7},{%8,%9},{%0,%1,%2,%3};"
        : "+f"(c[0]), "+f"(c[1]), "+f"(c[2]), "+f"(c[3])
        : "r"(a[0]), "r"(a[1]), "r"(a[2]), "r"(a[3]), "r"(b[0]), "r"(b[1]));
}

// ---------------- 1) transpose z: (8,1280,64,64) -> (8,4096,1280) ----------------
__global__ void transpose_kernel(const float* __restrict__ z)
{
    __shared__ float tile[32][33];
    const int b  = blockIdx.z;
    const int p0 = blockIdx.x * 32;
    const int c0 = blockIdx.y * 32;
    const float* src = z    + (size_t)b * 1280 * 4096;
    float*       dst = g_zt + (size_t)b * 4096 * 1280;
    const int tx = threadIdx.x, ty = threadIdx.y;
    #pragma unroll
    for (int i = 0; i < 4; i++)
        tile[ty + i*8][tx] = src[(size_t)(c0 + ty + i*8) * 4096 + p0 + tx];
    __syncthreads();
    #pragma unroll
    for (int i = 0; i < 4; i++)
        dst[(size_t)(p0 + ty + i*8) * 1280 + c0 + tx] = tile[tx][ty + i*8];
}

// ---------------- 1b) weight convert + transpose: W[K][N] f32 -> Wt[N][K] fp16 ----
__global__ void convt_kernel(const float* __restrict__ W,
                             __half* __restrict__ T, int K, int N)
{
    __shared__ float tile[32][33];
    const int n0 = blockIdx.x * 32;
    const int k0 = blockIdx.y * 32;
    const int tx = threadIdx.x, ty = threadIdx.y;
    #pragma unroll
    for (int i = 0; i < 4; i++)
        tile[ty + i*8][tx] = W[(size_t)(k0 + ty + i*8) * N + n0 + tx];
    __syncthreads();
    #pragma unroll
    for (int i = 0; i < 4; i++) {
        float v = tile[tx][ty + i*8];
        T[(size_t)(n0 + ty + i*8) * K + k0 + tx] = __float2half_rn(v);
    }
}

// ---------------- 2) RoIAlign 1x1, separable weights ----------------
__global__ void roi_align_kernel(const float* __restrict__ bboxes)
{
    __shared__ int   syi[18], sxi[18];
    __shared__ float syw[18], sxw[18];
    __shared__ int   sny, snx;
    __shared__ float sinv;

    const int r   = blockIdx.x;
    const int tid = threadIdx.x;

    if (tid == 0) {
        const float* bb = bboxes + (size_t)r * 4;
        float x1 = bb[0]*ROI_SCALE - 0.5f, y1 = bb[1]*ROI_SCALE - 0.5f;
        float x2 = bb[2]*ROI_SCALE - 0.5f, y2 = bb[3]*ROI_SCALE - 0.5f;
        float rw = x2 - x1, rh = y2 - y1;
        float gwf = fminf(fmaxf(ceilf(rw), 1.f), 8.f);
        float ghf = fminf(fmaxf(ceilf(rh), 1.f), 8.f);
        int gh = (int)ghf, gw = (int)gwf;
        sinv = 1.f / (ghf * gwf);

        float W[64];
        for (int j = 0; j < 64; j++) W[j] = 0.f;
        for (int i = 0; i < gh; i++) {
            float ys = y1 + ((float)i + 0.5f) * rh / ghf;
            if (ys < -1.f || ys > 64.f) continue;
            float cy = fmaxf(ys, 0.f);
            float l0 = floorf(cy);
            int yl = (int)fminf(l0, 63.f);
            int yh = (int)fminf(l0 + 1.f, 63.f);
            float fy = (l0 >= 63.f) ? 0.f : (cy - l0);
            W[yl] += 1.f - fy;
            W[yh] += fy;
        }
        int n = 0;
        for (int j = 0; j < 64; j++)
            if (W[j] != 0.f) { syi[n] = j; syw[n] = W[j]; n++; }
        sny = n;
        for (int j = 0; j < 64; j++) W[j] = 0.f;
        for (int i = 0; i < gw; i++) {
            float xs = x1 + ((float)i + 0.5f) * rw / gwf;
            if (xs < -1.f || xs > 64.f) continue;
            float cx = fmaxf(xs, 0.f);
            float l0 = floorf(cx);
            int xl = (int)fminf(l0, 63.f);
            int xh = (int)fminf(l0 + 1.f, 63.f);
            float fx = (l0 >= 63.f) ? 0.f : (cx - l0);
            W[xl] += 1.f - fx;
            W[xh] += fx;
        }
        n = 0;
        for (int j = 0; j < 64; j++)
            if (W[j] != 0.f) { sxi[n] = j; sxw[n] = W[j]; n++; }
        snx = n;
    }
    __syncthreads();

    const int b = r >> 7;
    const float* base = g_zt + (size_t)b * 4096 * 1280 + tid;
    float acc[5] = {0.f, 0.f, 0.f, 0.f, 0.f};

    const int NY = sny, NX = snx;
    for (int iy = 0; iy < NY; iy++) {
        const float* py = base + (size_t)syi[iy] * (64 * 1280);
        float t[5] = {0.f, 0.f, 0.f, 0.f, 0.f};
        for (int ix = 0; ix < NX; ix++) {
            const float* p = py + (size_t)sxi[ix] * 1280;
            const float w = sxw[ix];
            #pragma unroll
            for (int k = 0; k < 5; k++) t[k] += w * p[k * 256];
        }
        const float wy = syw[iy];
        #pragma unroll
        for (int k = 0; k < 5; k++) acc[k] += wy * t[k];
    }
    #pragma unroll
    for (int k = 0; k < 5; k++) {
        float v = acc[k] * sinv;
        __half h, l; fp16_split(v, h, l);
        size_t idx = (size_t)r * 1280 + tid + k * 256;
        g_Xh[idx] = h; g_Xl[idx] = l;
    }
}

// ---------------- 3) fp16 mma.sync GEMM, ldmatrix + BK=32, 3-stage ----------------
// ASPLIT: 1 = A given as hi+lo fp16 pair (split-2), 0 = single fp16 A.
// OUT: 1 = relu + single fp16 store, 3 = fp32 split-K partial (no bias)
#define ROWB 80
#define GBM 128

template<int ASPLIT, int OUT>
__global__ __launch_bounds__(256, 2)
void mma_gemm(const __half* __restrict__ Ah, const __half* __restrict__ Al,
              const __half* __restrict__ Bh,
              const float* __restrict__ bias,
              float* __restrict__ Cf, __half* __restrict__ Ch,
              int K, int Klen, int ldc)
{
    constexpr int ALOFF = GBM * ROWB;                     // only used if ASPLIT
    constexpr int BHOFF = (1 + ASPLIT) * GBM * ROWB;
    constexpr int STG   = ((1 + ASPLIT) * GBM + 128) * ROWB;

    extern __shared__ char smem[];
    const uint32_t sb = (uint32_t)__cvta_generic_to_shared(smem);

    const int tid  = threadIdx.x;
    const int wid  = tid >> 5, lane = tid & 31;
    const int wm   = (wid >> 2) * 64;
    const int wn   = (wid & 3) * 32;
    const int qrow = lane >> 2, qcol = lane & 3;
    const int m0   = blockIdx.y * GBM;
    const int n0   = blockIdx.x * 128;
    const int koff = blockIdx.z * Klen;

    const uint32_t aoff = (uint32_t)((wm + (lane & 15)) * ROWB + (lane >> 4) * 16);
    const uint32_t boff = (uint32_t)((wn + ((lane >> 4) << 3) + (lane & 7)) * ROWB
                                     + ((lane >> 3) & 1) * 16);

    float acc[4][4][4];
    #pragma unroll
    for (int i = 0; i < 4; i++)
        #pragma unroll
        for (int j = 0; j < 4; j++)
            #pragma unroll
            for (int q = 0; q < 4; q++) acc[i][j][q] = 0.f;

    auto load_stage = [&](int st, int kc) {
        const uint32_t base = sb + st * STG;
        #pragma unroll
        for (int i = 0; i < 2; i++) {
            int f = tid + i * 256;
            int row = f >> 2, c = f & 3;
            size_t g = (size_t)(m0 + row) * K + koff + kc + c * 8;
            uint32_t so = (uint32_t)(row * ROWB + c * 16);
            cpasync16(base + so, Ah + g);
            if (ASPLIT) cpasync16(base + ALOFF + so, Al + g);
        }
        #pragma unroll
        for (int i = 0; i < 2; i++) {
            int f = tid + i * 256;
            int row = f >> 2, c = f & 3;
            size_t g = (size_t)(n0 + row) * K + koff + kc + c * 8;
            uint32_t so = (uint32_t)(row * ROWB + c * 16);
            cpasync16(base + BHOFF + so, Bh + g);
        }
        asm volatile("cp.async.commit_group;\n" ::: "memory");
    };

    const int S = Klen >> 5;
    load_stage(0, 0);
    load_stage(1, 32);

    for (int s = 0; s < S; s++) {
        if (s + 2 < S) {
            asm volatile("cp.async.wait_group 1;\n" ::: "memory");
        } else {
            asm volatile("cp.async.wait_group 0;\n" ::: "memory");
        }
        __syncthreads();
        if (s + 2 < S) load_stage((s + 2) % 3, (s + 2) * 32);

        const uint32_t base = sb + (s % 3) * STG;
        #pragma unroll
        for (int ks = 0; ks < 2; ks++) {
            uint32_t bh[2][4];
            #pragma unroll
            for (int p = 0; p < 2; p++)
                ldsm4(bh[p], base + BHOFF + boff + p * (16*ROWB) + ks * 32);
            #pragma unroll
            for (int mt = 0; mt < 4; mt++) {
                uint32_t ah[4];
                ldsm4(ah, base + aoff + mt * (16*ROWB) + ks * 32);
                uint32_t al[4];
                if (ASPLIT) ldsm4(al, base + ALOFF + aoff + mt * (16*ROWB) + ks * 32);
                #pragma unroll
                for (int nt = 0; nt < 4; nt++) {
                    const uint32_t* bp = &bh[nt >> 1][(nt & 1) * 2];
                    mma16816(acc[mt][nt], ah, bp);
                    if (ASPLIT) mma16816(acc[mt][nt], al, bp);
                }
            }
        }
        __syncthreads();
    }

    float* Cfz = (OUT == 3) ? (Cf + (size_t)blockIdx.z * 1024 * 1024) : Cf;

    #pragma unroll
    for (int mt = 0; mt < 4; mt++) {
        int r0 = m0 + wm + mt * 16 + qrow;
        #pragma unroll
        for (int nt = 0; nt < 4; nt++) {
            int c = n0 + wn + nt * 8 + qcol * 2;
            float bv0 = (OUT == 3) ? 0.f : bias[c];
            float bv1 = (OUT == 3) ? 0.f : bias[c + 1];
            float v00 = acc[mt][nt][0] + bv0;
            float v01 = acc[mt][nt][1] + bv1;
            float v10 = acc[mt][nt][2] + bv0;
            float v11 = acc[mt][nt][3] + bv1;
            if (OUT == 1) {
                v00 = fmaxf(v00, 0.f); v01 = fmaxf(v01, 0.f);
                v10 = fmaxf(v10, 0.f); v11 = fmaxf(v11, 0.f);
                size_t i0 = (size_t)r0 * ldc + c;
                size_t i1 = (size_t)(r0 + 8) * ldc + c;
                *(__half2*)(Ch + i0) = __halves2half2(__float2half_rn(v00), __float2half_rn(v01));
                *(__half2*)(Ch + i1) = __halves2half2(__float2half_rn(v10), __float2half_rn(v11));
            } else {
                size_t i0 = (size_t)r0 * ldc + c;
                size_t i1 = (size_t)(r0 + 8) * ldc + c;
                Cfz[i0] = v00; Cfz[i0 + 1] = v01;
                Cfz[i1] = v10; Cfz[i1 + 1] = v11;
            }
        }
    }
}

// ---------------- 3b) split-K reduce ----------------
// OUT: 2 = single fp16 to CAT (ldc 2048), 0 = f32 to out (ldc 1024)
template<int OUT>
__global__ __launch_bounds__(256)
void reduce_k(const float* __restrict__ P, const float* __restrict__ bias,
              float* __restrict__ Cf, __half* __restrict__ Ch, int ldc)
{
    const int idx = blockIdx.x * 256 + threadIdx.x;   // f4 index
    const int r   = idx >> 8;
    const int c   = (idx & 255) * 4;
    const size_t p = (size_t)r * 1024 + c;
    float4 a = *(const float4*)(P + p);
    float4 b = *(const float4*)(P + 1024ul*1024 + p);
    float4 bv = *(const float4*)(bias + c);
    float v0 = a.x + b.x + bv.x;
    float v1 = a.y + b.y + bv.y;
    float v2 = a.z + b.z + bv.z;
    float v3 = a.w + b.w + bv.w;
    if (OUT == 0) {
        *(float4*)(Cf + (size_t)r * ldc + c) = make_float4(v0, v1, v2, v3);
    } else {
        size_t o = (size_t)r * ldc + c;
        *(__half2*)(Ch + o)     = __halves2half2(__float2half_rn(v0), __float2half_rn(v1));
        *(__half2*)(Ch + o + 2) = __halves2half2(__float2half_rn(v2), __float2half_rn(v3));
    }
}

// ---------------- 4) bbox-size embedding MLP ----------------
__global__ __launch_bounds__(256) void mlp_e_kernel(
    const float* __restrict__ bboxes,
    const float* __restrict__ S1, const float* __restrict__ sb1,
    const float* __restrict__ S2, const float* __restrict__ sb2,
    const float* __restrict__ S3, const float* __restrict__ sb3)
{
    __shared__ float e1[16][64];
    __shared__ float e2[16][256];
    __shared__ float sbh[16], sbw[16];

    const int r0  = blockIdx.x * 16;
    const int tid = threadIdx.x;

    if (tid < 16) {
        const float* bb = bboxes + (size_t)(r0 + tid) * 4;
        sbh[tid] = bb[3] - bb[1];
        sbw[tid] = bb[2] - bb[0];
    }
    __syncthreads();

    for (int i = tid; i < 16*64; i += 256) {
        int row = i >> 6, col = i & 63;
        float v = sbh[row] * S1[col] + sbw[row] * S1[64 + col] + sb1[col];
        e1[row][col] = fmaxf(v, 0.f);
    }
    __syncthreads();

    {
        float a[16];
        const float bv = sb2[tid];
        #pragma unroll
        for (int r = 0; r < 16; r++) a[r] = bv;
        for (int k = 0; k < 64; k++) {
            const float s = S2[(size_t)k * 256 + tid];
            #pragma unroll
            for (int r = 0; r < 16; r++) a[r] += e1[r][k] * s;
        }
        #pragma unroll
        for (int r = 0; r < 16; r++) e2[r][tid] = fmaxf(a[r], 0.f);
    }
    __syncthreads();

    for (int cc = 0; cc < 4; cc++) {
        const int col = tid + cc * 256;
        float a[16];
        const float bv = sb3[col];
        #pragma unroll
        for (int r = 0; r < 16; r++) a[r] = bv;
        for (int k = 0; k < 256; k++) {
            const float s = S3[(size_t)k * 1024 + col];
            #pragma unroll
            for (int r = 0; r < 16; r++) a[r] += e2[r][k] * s;
        }
        #pragma unroll
        for (int r = 0; r < 16; r++)
            g_CAT[(size_t)(r0 + r) * 2048 + 1024 + col] = __float2half_rn(a[r]);
    }
}

// ---------------- launch ----------------
extern "C" void kernel_launch(void* const* d_in, const int* in_sizes, int n_in,
                              void* d_out, int out_size)
{
    const float* z      = (const float*)d_in[0];
    const float* bboxes = (const float*)d_in[1];
    const float* W1     = (const float*)d_in[2];
    const float* b1     = (const float*)d_in[3];
    const float* W2     = (const float*)d_in[4];
    const float* b2     = (const float*)d_in[5];
    const float* S1     = (const float*)d_in[6];
    const float* sb1    = (const float*)d_in[7];
    const float* S2     = (const float*)d_in[8];
    const float* sb2    = (const float*)d_in[9];
    const float* S3     = (const float*)d_in[10];
    const float* sb3    = (const float*)d_in[11];
    const float* O      = (const float*)d_in[12];
    const float* ob     = (const float*)d_in[13];
    float* out = (float*)d_out;

    __half *Xh, *Xl, *H, *CAT, *W1t, *W2t, *Ot;
    float* P;
    cudaGetSymbolAddress((void**)&Xh,  g_Xh);
    cudaGetSymbolAddress((void**)&Xl,  g_Xl);
    cudaGetSymbolAddress((void**)&H,   g_H);
    cudaGetSymbolAddress((void**)&CAT, g_CAT);
    cudaGetSymbolAddress((void**)&W1t, g_W1t);
    cudaGetSymbolAddress((void**)&W2t, g_W2t);
    cudaGetSymbolAddress((void**)&Ot,  g_Ot);
    cudaGetSymbolAddress((void**)&P,   g_P);

    constexpr int SMEM_S = (2*GBM + 128) * ROWB * 3;   // 92160 (ASPLIT=1)
    constexpr int SMEM_N = (GBM + 128) * ROWB * 3;     // 61440 (ASPLIT=0)

    static bool attr_set = false;
    if (!attr_set) {
        cudaFuncSetAttribute((const void*)mma_gemm<1,1>, cudaFuncAttributeMaxDynamicSharedMemorySize, SMEM_S);
        cudaFuncSetAttribute((const void*)mma_gemm<0,3>, cudaFuncAttributeMaxDynamicSharedMemorySize, SMEM_N);
        attr_set = true;
    }

    // weight conversion + transpose (fp16)
    convt_kernel<<<dim3(5120/32, 1280/32), dim3(32, 8)>>>(W1, W1t, 1280, 5120);
    convt_kernel<<<dim3(1024/32, 5120/32), dim3(32, 8)>>>(W2, W2t, 5120, 1024);
    convt_kernel<<<dim3(1024/32, 2048/32), dim3(32, 8)>>>(O,  Ot,  2048, 1024);

    // z NCHW -> NHWC
    transpose_kernel<<<dim3(128, 40, 8), dim3(32, 8)>>>(z);

    // RoIAlign -> X hi/lo (separable)
    roi_align_kernel<<<1024, 256>>>(bboxes);

    // bbox MLP -> CAT[:,1024:2048] (single fp16)
    mlp_e_kernel<<<64, 256>>>(bboxes, S1, sb1, S2, sb2, S3, sb3);

    // H = relu(X @ W1 + b1)   (A split-2; store single fp16)
    mma_gemm<1,1><<<dim3(5120/128, 1024/128), 256, SMEM_S>>>(
        Xh, Xl, W1t, b1, nullptr, H, 1280, 1280, 5120);

    // P = H @ W2 (single-A, split-K 2x2560) -> CAT[:, :1024] = fp16(P0+P1+b2)
    mma_gemm<0,3><<<dim3(1024/128, 1024/128, 2), 256, SMEM_N>>>(
        H, nullptr, W2t, nullptr, P, nullptr, 5120, 2560, 1024);
    reduce_k<2><<<1024, 256>>>(P, b2, nullptr, CAT, 2048);

    // P = CAT @ O (single-A, split-K 2x1024) -> out = P0+P1+ob
    mma_gemm<0,3><<<dim3(1024/128, 1024/128, 2), 256, SMEM_N>>>(
        CAT, nullptr, Ot, nullptr, P, nullptr, 2048, 1024, 1024);
    reduce_k<0><<<1024, 256>>>(P, ob, out, nullptr, 1024);
}